// round 12
// baseline (speedup 1.0000x reference)
#include <cuda_runtime.h>
#include <cuda_bf16.h>
#include <cuda_fp16.h>
#include <math.h>
#include <stdint.h>

// Problem constants
#define B_   2
#define S_   2048
#define C_   2048
#define H_   16
#define DH_  128
#define QSCALE 0.08838834764831845f

// Scratch (device globals)
__device__ __half g_A2[(size_t)B_*S_*2*C_];      // [4096][4096] = [hi|lo] fp16
__device__ __half g_B2[(size_t)3*C_*2*C_];       // [6144][4096] = [hi|lo] fp16
__device__ __nv_bfloat16 g_Q2[(size_t)B_*H_*S_*256];
__device__ __nv_bfloat16 g_K2[(size_t)B_*H_*S_*256];
__device__ __half        g_V2[(size_t)B_*H_*S_*256];   // fp16 [hi|lo]
__device__ float g_cos[S_*64];
__device__ float g_sin[S_*64];

#define AK2 (2*C_)        // 4096: row stride of A2/B2

__device__ __forceinline__ uint32_t smem_u32(const void* p) {
    uint32_t a;
    asm("{ .reg .u64 t; cvta.to.shared.u64 t, %1; cvt.u32.u64 %0, t; }" : "=r"(a) : "l"(p));
    return a;
}
__device__ __forceinline__ void cp16(uint32_t dst, const void* src) {
    asm volatile("cp.async.cg.shared.global [%0], [%1], 16;" :: "r"(dst), "l"(src));
}
__device__ __forceinline__ void ldm4(uint32_t& r0, uint32_t& r1, uint32_t& r2,
                                     uint32_t& r3, uint32_t addr) {
    asm volatile("ldmatrix.sync.aligned.m8n8.x4.shared.b16 {%0,%1,%2,%3}, [%4];"
        : "=r"(r0), "=r"(r1), "=r"(r2), "=r"(r3) : "r"(addr));
}
__device__ __forceinline__ void ldm4t(uint32_t& r0, uint32_t& r1, uint32_t& r2,
                                      uint32_t& r3, uint32_t addr) {
    asm volatile("ldmatrix.sync.aligned.m8n8.x4.trans.shared.b16 {%0,%1,%2,%3}, [%4];"
        : "=r"(r0), "=r"(r1), "=r"(r2), "=r"(r3) : "r"(addr));
}
__device__ __forceinline__ void mma_bf16(float* c, uint32_t a0, uint32_t a1,
                                         uint32_t a2, uint32_t a3,
                                         uint32_t b0, uint32_t b1) {
    asm volatile("mma.sync.aligned.m16n8k16.row.col.f32.bf16.bf16.f32 "
        "{%0,%1,%2,%3}, {%4,%5,%6,%7}, {%8,%9}, {%0,%1,%2,%3};"
        : "+f"(c[0]), "+f"(c[1]), "+f"(c[2]), "+f"(c[3])
        : "r"(a0), "r"(a1), "r"(a2), "r"(a3), "r"(b0), "r"(b1));
}
__device__ __forceinline__ void mma_f16(float* c, uint32_t a0, uint32_t a1,
                                        uint32_t a2, uint32_t a3,
                                        uint32_t b0, uint32_t b1) {
    asm volatile("mma.sync.aligned.m16n8k16.row.col.f32.f16.f16.f32 "
        "{%0,%1,%2,%3}, {%4,%5,%6,%7}, {%8,%9}, {%0,%1,%2,%3};"
        : "+f"(c[0]), "+f"(c[1]), "+f"(c[2]), "+f"(c[3])
        : "r"(a0), "r"(a1), "r"(a2), "r"(a3), "r"(b0), "r"(b1));
}
__device__ __forceinline__ void split_pack(float x, float y, uint32_t& hi, uint32_t& lo) {
    __nv_bfloat16 hx = __float2bfloat16(x);
    __nv_bfloat16 hy = __float2bfloat16(y);
    __nv_bfloat16 lx = __float2bfloat16(x - __bfloat162float(hx));
    __nv_bfloat16 ly = __float2bfloat16(y - __bfloat162float(hy));
    hi = (uint32_t)*(uint16_t*)&hx | ((uint32_t)*(uint16_t*)&hy << 16);
    lo = (uint32_t)*(uint16_t*)&lx | ((uint32_t)*(uint16_t*)&ly << 16);
}
__device__ __forceinline__ uint32_t pack_h2(float x, float y) {
    __half2 h = __floats2half2_rn(x, y);
    return *(uint32_t*)&h;
}
__device__ __forceinline__ void split_pack_h(float x, float y, uint32_t& hi, uint32_t& lo) {
    __half hx = __float2half(x);
    __half hy = __float2half(y);
    __half lx = __float2half(x - __half2float(hx));
    __half ly = __float2half(y - __half2float(hy));
    hi = (uint32_t)*(uint16_t*)&hx | ((uint32_t)*(uint16_t*)&hy << 16);
    lo = (uint32_t)*(uint16_t*)&lx | ((uint32_t)*(uint16_t*)&ly << 16);
}
__device__ __forceinline__ void split_st(__nv_bfloat16* dst, int off, float v) {
    __nv_bfloat16 hi = __float2bfloat16(v);
    dst[off]       = hi;
    dst[off + 128] = __float2bfloat16(v - __bfloat162float(hi));
}
__device__ __forceinline__ void split_st_h(__half* dst, int off, float v) {
    __half hi = __float2half(v);
    dst[off]       = hi;
    dst[off + 128] = __float2half(v - __half2float(hi));
}

// ---------------------------------------------------------------------------
// RoPE table
// ---------------------------------------------------------------------------
__global__ void rope_table_kernel() {
    int idx = blockIdx.x * blockDim.x + threadIdx.x;
    if (idx >= S_*64) return;
    int s = idx >> 6, d = idx & 63;
    float invf = (float)pow(10000.0, -(double)d / 64.0);
    float ang  = (float)s * invf;
    double a = (double)ang;
    g_cos[idx] = (float)cos(a);
    g_sin[idx] = (float)sin(a);
}

// ---------------------------------------------------------------------------
// fp16 split conversions: [hi|lo] layouts (stride AK2)
// ---------------------------------------------------------------------------
__global__ void conv_A_kernel(const float* __restrict__ A) {
    int idx = blockIdx.x * blockDim.x + threadIdx.x;
    int k = idx & (C_-1);
    int m = idx >> 11;
    float v = A[idx];
    __half hi = __float2half(v);
    __half lo = __float2half(v - __half2float(hi));
    size_t base = (size_t)m * AK2;
    g_A2[base + k]       = hi;
    g_A2[base + C_ + k]  = lo;
}

__global__ void conv_B_kernel(const float* __restrict__ W, int N) {
    __shared__ float tile[32][33];
    int n0 = blockIdx.x * 32, k0 = blockIdx.y * 32;
    int tx = threadIdx.x, ty = threadIdx.y;
    #pragma unroll
    for (int j = 0; j < 4; j++)
        tile[ty + 8*j][tx] = W[(size_t)(k0 + ty + 8*j) * N + n0 + tx];
    __syncthreads();
    #pragma unroll
    for (int j = 0; j < 4; j++) {
        int n = n0 + ty + 8*j;
        int k = k0 + tx;
        float v = tile[tx][ty + 8*j];
        __half hi = __float2half(v);
        __half lo = __float2half(v - __half2float(hi));
        size_t base = (size_t)n * AK2;
        g_B2[base + k]      = hi;
        g_B2[base + C_ + k] = lo;
    }
}

// ---------------------------------------------------------------------------
// GEMM config (R10 structure): fp16 2-term via virtual K=4096,
// GBK=64, 3-stage, interleaved cp.async, batched LDSM per kc.
// ---------------------------------------------------------------------------
#define GBM 128
#define GBN 128
#define GBK 64
#define LDT 72
#define OP_ELEMS (128*LDT)
#define NSTG 3
#define GEMM_NT 64                       // 4096/64
#define GEMM_SMEM (NSTG*2*OP_ELEMS*2)    // 110592 B

#define GEMM_MAINLOOP(A_, Bt_)                                                   \
    const int tid  = threadIdx.x;                                                \
    const int lane = tid & 31, wid = tid >> 5;                                   \
    const int wm = wid >> 2, wn = wid & 3;                                       \
    const int bm = blockIdx.y * GBM, bn = blockIdx.x * GBN;                      \
    const uint32_t aBase = smem_u32(gsm);                                        \
    const uint32_t bBase = smem_u32(gsm + NSTG*OP_ELEMS);                        \
    const uint32_t aRowSel = (lane & 15), aColSel = (lane >> 4) * 8;             \
    const uint32_t bRowSel = ((lane >> 4) * 8) + (lane & 7);                     \
    const uint32_t bColSel = ((lane >> 3) & 1) * 8;                              \
    const int rg = tid >> 3, cg8 = (tid & 7) * 8;                                \
    float acc[4][4][4];                                                          \
    _Pragma("unroll")                                                            \
    for (int i = 0; i < 4; i++)                                                  \
        _Pragma("unroll")                                                        \
        for (int j = 0; j < 4; j++)                                              \
            _Pragma("unroll")                                                    \
            for (int r = 0; r < 4; r++) acc[i][j][r] = 0.f;                      \
    auto issue_part = [&](int stg, int kt, int p) {                              \
        const int kv = kt * GBK;                                                 \
        const int koffA = kv & (C_-1);                                           \
        const int koffB = kv;                                                    \
        const uint32_t aD = aBase + stg * OP_ELEMS * 2;                          \
        const uint32_t bD = bBase + stg * OP_ELEMS * 2;                          \
        const int r = rg + p * 32;                                               \
        cp16(aD + (r*LDT + cg8)*2, A_  + (size_t)(bm + r)*AK2 + koffA + cg8);    \
        cp16(bD + (r*LDT + cg8)*2, Bt_ + (size_t)(bn + r)*AK2 + koffB + cg8);    \
    };                                                                           \
    _Pragma("unroll")                                                            \
    for (int p = 0; p < 4; p++) issue_part(0, 0, p);                             \
    asm volatile("cp.async.commit_group;");                                      \
    _Pragma("unroll")                                                            \
    for (int p = 0; p < 4; p++) issue_part(1, 1, p);                             \
    asm volatile("cp.async.commit_group;");                                      \
    for (int kt = 0; kt < GEMM_NT; kt++) {                                       \
        if (kt < GEMM_NT - 1) asm volatile("cp.async.wait_group 1;");            \
        else                  asm volatile("cp.async.wait_group 0;");            \
        __syncthreads();                                                         \
        const bool pf = (kt + 2 < GEMM_NT);                                      \
        const int stg2 = (kt + 2) % NSTG;                                        \
        const uint32_t aS = aBase + (kt % NSTG) * OP_ELEMS * 2;                  \
        const uint32_t bS = bBase + (kt % NSTG) * OP_ELEMS * 2;                  \
        _Pragma("unroll")                                                        \
        for (int kc = 0; kc < 4; kc++) {                                         \
            if (pf) issue_part(stg2, kt + 2, kc);                                \
            /* batched LDSM: all 6 loads first, then 16 MMAs */                  \
            uint32_t bf[4][2];                                                   \
            _Pragma("unroll")                                                    \
            for (int np = 0; np < 2; np++) {                                     \
                uint32_t addr = bS + ((wn*32 + np*16 + bRowSel) * LDT            \
                                      + kc*16 + bColSel) * 2;                    \
                uint32_t r0, r1, r2, r3;                                         \
                ldm4(r0, r1, r2, r3, addr);                                      \
                bf[np*2+0][0] = r0; bf[np*2+0][1] = r1;                          \
                bf[np*2+1][0] = r2; bf[np*2+1][1] = r3;                          \
            }                                                                    \
            uint32_t af[4][4];                                                   \
            _Pragma("unroll")                                                    \
            for (int mt = 0; mt < 4; mt++) {                                     \
                uint32_t addr = aS + ((wm*64 + mt*16 + aRowSel) * LDT            \
                                      + kc*16 + aColSel) * 2;                    \
                ldm4(af[mt][0], af[mt][1], af[mt][2], af[mt][3], addr);          \
            }                                                                    \
            _Pragma("unroll")                                                    \
            for (int mt = 0; mt < 4; mt++)                                       \
                _Pragma("unroll")                                                \
                for (int nt = 0; nt < 4; nt++)                                   \
                    mma_f16(acc[mt][nt], af[mt][0], af[mt][1],                   \
                            af[mt][2], af[mt][3], bf[nt][0], bf[nt][1]);         \
        }                                                                        \
        if (pf) asm volatile("cp.async.commit_group;");                          \
    }

// ---------------------------------------------------------------------------
// GEMM1 (fused): qkv tile -> RoPE + scale + split -> g_Q2/K2(bf16), g_V2(fp16)
// ---------------------------------------------------------------------------
#define STG_LD 129

__global__ void __launch_bounds__(256, 2) gemm1_fused(
    const __half* __restrict__ A, const __half* __restrict__ Bt)
{
    extern __shared__ __half gsm[];
    GEMM_MAINLOOP(A, Bt)

    __syncthreads();
    float* st = (float*)gsm;                    // 128 x 129 fp32 = 66048 B
    #pragma unroll
    for (int mt = 0; mt < 4; mt++) {
        const int r0 = wm*64 + mt*16 + (lane >> 2);
        #pragma unroll
        for (int nt = 0; nt < 4; nt++) {
            const int col = wn*32 + nt*8 + (lane & 3)*2;
            st[r0*STG_LD + col]       = acc[mt][nt][0];
            st[r0*STG_LD + col + 1]   = acc[mt][nt][1];
            st[(r0+8)*STG_LD + col]   = acc[mt][nt][2];
            st[(r0+8)*STG_LD + col+1] = acc[mt][nt][3];
        }
    }
    __syncthreads();

    const int sec = bn >> 11;                   // 0=K, 1=Q, 2=V
    const int h   = (bn & (C_-1)) >> 7;
    const float scl = (sec == 1) ? QSCALE : 1.f;

    #pragma unroll
    for (int i = 0; i < 32; i++) {
        int p = tid + i*256;
        int r = p >> 6, d = p & 63;
        int grow = bm + r;
        int stok = grow & (S_-1), bb = grow >> 11;
        float t1 = st[r*STG_LD + d], t2 = st[r*STG_LD + d + 64];
        size_t orow = ((size_t)(bb*H_ + h) * S_ + stok) * 256;
        if (sec == 2) {
            split_st_h(g_V2 + orow, d, t1);
            split_st_h(g_V2 + orow, d + 64, t2);
        } else {
            float c  = g_cos[stok*64 + d];
            float sn = g_sin[stok*64 + d];
            float o1 = (t1*c - t2*sn) * scl;
            float o2 = (t2*c + t1*sn) * scl;
            __nv_bfloat16* dstArr = (sec == 0) ? g_K2 : g_Q2;
            split_st(dstArr + orow, d, o1);
            split_st(dstArr + orow, d + 64, o2);
        }
    }
}

// ---------------------------------------------------------------------------
// GEMM2 (plain): writes fp32 C
// ---------------------------------------------------------------------------
__global__ void __launch_bounds__(256, 2) gemm_f16_2term(
    const __half* __restrict__ A, const __half* __restrict__ Bt,
    float* __restrict__ C, int N)
{
    extern __shared__ __half gsm[];
    GEMM_MAINLOOP(A, Bt)

    #pragma unroll
    for (int mt = 0; mt < 4; mt++) {
        const int r0 = bm + wm*64 + mt*16 + (lane >> 2);
        #pragma unroll
        for (int nt = 0; nt < 4; nt++) {
            const int col = bn + wn*32 + nt*8 + (lane & 3)*2;
            *(float2*)(C + (size_t)r0 * N + col) =
                make_float2(acc[mt][nt][0], acc[mt][nt][1]);
            *(float2*)(C + (size_t)(r0 + 8) * N + col) =
                make_float2(acc[mt][nt][2], acc[mt][nt][3]);
        }
    }
}

// ---------------------------------------------------------------------------
// Tensor-core flash attention: QK bf16 3-term, PV fp16 2-term.
// ---------------------------------------------------------------------------
#define ABR 128
#define ABC 64
#define ALD 264
#define QS_ELEMS (ABR*ALD)
#define KV_ELEMS (ABC*ALD)
#define ATT_SMEM ((QS_ELEMS + 4*KV_ELEMS)*2)

__global__ void __launch_bounds__(256, 1) attn_mma_kernel() {
    extern __shared__ __nv_bfloat16 attsm[];
    __nv_bfloat16* Qs = attsm;
    __nv_bfloat16* Ks = attsm + QS_ELEMS;
    __nv_bfloat16* Vs = attsm + QS_ELEMS + 2*KV_ELEMS;   // holds fp16 bits

    const int tid = threadIdx.x, lane = tid & 31, wid = tid >> 5;
    const int qt = gridDim.x - 1 - blockIdx.x;
    const int bh = blockIdx.y;
    const int q0 = qt * ABR;
    const size_t gbase = (size_t)bh * S_ * 256;

    const uint32_t qsB = smem_u32(Qs), ksB = smem_u32(Ks), vsB = smem_u32(Vs);

    {
        const __nv_bfloat16* qsrc = g_Q2 + gbase + (size_t)q0 * 256;
        #pragma unroll
        for (int i = 0; i < 16; i++) {
            int ch = tid + i*256;
            int r = ch >> 5, c8 = (ch & 31) * 8;
            cp16(qsB + (r*ALD + c8)*2, qsrc + (size_t)r*256 + c8);
        }
        const __nv_bfloat16* ksrc = g_K2 + gbase;
        const __half*        vsrc = g_V2 + gbase;
        #pragma unroll
        for (int i = 0; i < 8; i++) {
            int ch = tid + i*256;
            int r = ch >> 5, c8 = (ch & 31) * 8;
            cp16(ksB + (r*ALD + c8)*2, ksrc + (size_t)r*256 + c8);
            cp16(vsB + (r*ALD + c8)*2, vsrc + (size_t)r*256 + c8);
        }
        asm volatile("cp.async.commit_group;");
    }

    const int lr = lane >> 2, lc = lane & 3;
    const int wq = wid * 16;

    float m0 = -1e30f, m1 = -1e30f, l0 = 0.f, l1 = 0.f;
    float o[16][4];
    #pragma unroll
    for (int i = 0; i < 16; i++)
        #pragma unroll
        for (int j = 0; j < 4; j++) o[i][j] = 0.f;

    const int nkb = 2*qt + 2;

    for (int kb = 0; kb < nkb; kb++) {
        const int s = kb & 1;
        if (kb + 1 < nkb) {
            const int ns = s ^ 1;
            const __nv_bfloat16* ksrc = g_K2 + gbase + (size_t)((kb+1)*ABC) * 256;
            const __half*        vsrc = g_V2 + gbase + (size_t)((kb+1)*ABC) * 256;
            uint32_t kd = ksB + ns*KV_ELEMS*2, vd = vsB + ns*KV_ELEMS*2;
            #pragma unroll
            for (int i = 0; i < 8; i++) {
                int ch = tid + i*256;
                int r = ch >> 5, c8 = (ch & 31) * 8;
                cp16(kd + (r*ALD + c8)*2, ksrc + (size_t)r*256 + c8);
                cp16(vd + (r*ALD + c8)*2, vsrc + (size_t)r*256 + c8);
            }
            asm volatile("cp.async.commit_group;");
            asm volatile("cp.async.wait_group 1;");
        } else {
            asm volatile("cp.async.wait_group 0;");
        }
        __syncthreads();

        const uint32_t ks0 = ksB + s*KV_ELEMS*2;
        const uint32_t vs0 = vsB + s*KV_ELEMS*2;

        float sacc[8][4];
        #pragma unroll
        for (int i = 0; i < 8; i++)
            #pragma unroll
            for (int j = 0; j < 4; j++) sacc[i][j] = 0.f;

        #pragma unroll
        for (int kc = 0; kc < 8; kc++) {
            uint32_t qaddr = qsB + ((wq + (lane & 15))*ALD + kc*16 + (lane >> 4)*8)*2;
            uint32_t qh0,qh1,qh2,qh3, ql0,ql1,ql2,ql3;
            ldm4(qh0,qh1,qh2,qh3, qaddr);
            ldm4(ql0,ql1,ql2,ql3, qaddr + 128*2);
            #pragma unroll
            for (int ntp = 0; ntp < 4; ntp++) {
                uint32_t baddr = ks0 + ((ntp*16 + (lane>>4)*8 + (lane&7))*ALD
                                        + kc*16 + ((lane>>3)&1)*8)*2;
                uint32_t h0,h1,h2,h3, e0,e1,e2,e3;
                ldm4(h0,h1,h2,h3, baddr);
                ldm4(e0,e1,e2,e3, baddr + 128*2);
                mma_bf16(sacc[2*ntp],   qh0,qh1,qh2,qh3, h0,h1);
                mma_bf16(sacc[2*ntp],   qh0,qh1,qh2,qh3, e0,e1);
                mma_bf16(sacc[2*ntp],   ql0,ql1,ql2,ql3, h0,h1);
                mma_bf16(sacc[2*ntp+1], qh0,qh1,qh2,qh3, h2,h3);
                mma_bf16(sacc[2*ntp+1], qh0,qh1,qh2,qh3, e2,e3);
                mma_bf16(sacc[2*ntp+1], ql0,ql1,ql2,ql3, h2,h3);
            }
        }

        const int r0 = q0 + wq + lr, r1 = r0 + 8;
        if (kb >= 2*qt) {
            #pragma unroll
            for (int nt = 0; nt < 8; nt++) {
                int key = kb*ABC + nt*8 + 2*lc;
                if (key     > r0) sacc[nt][0] = -1e30f;
                if (key + 1 > r0) sacc[nt][1] = -1e30f;
                if (key     > r1) sacc[nt][2] = -1e30f;
                if (key + 1 > r1) sacc[nt][3] = -1e30f;
            }
        }

        float mx0 = m0, mx1 = m1;
        #pragma unroll
        for (int nt = 0; nt < 8; nt++) {
            mx0 = fmaxf(mx0, fmaxf(sacc[nt][0], sacc[nt][1]));
            mx1 = fmaxf(mx1, fmaxf(sacc[nt][2], sacc[nt][3]));
        }
        mx0 = fmaxf(mx0, __shfl_xor_sync(0xffffffffu, mx0, 1));
        mx0 = fmaxf(mx0, __shfl_xor_sync(0xffffffffu, mx0, 2));
        mx1 = fmaxf(mx1, __shfl_xor_sync(0xffffffffu, mx1, 1));
        mx1 = fmaxf(mx1, __shfl_xor_sync(0xffffffffu, mx1, 2));
        float a0 = __expf(m0 - mx0), a1 = __expf(m1 - mx1);
        m0 = mx0; m1 = mx1;

        float s0 = 0.f, s1 = 0.f;
        #pragma unroll
        for (int nt = 0; nt < 8; nt++) {
            sacc[nt][0] = __expf(sacc[nt][0] - m0); s0 += sacc[nt][0];
            sacc[nt][1] = __expf(sacc[nt][1] - m0); s0 += sacc[nt][1];
            sacc[nt][2] = __expf(sacc[nt][2] - m1); s1 += sacc[nt][2];
            sacc[nt][3] = __expf(sacc[nt][3] - m1); s1 += sacc[nt][3];
        }
        s0 += __shfl_xor_sync(0xffffffffu, s0, 1);
        s0 += __shfl_xor_sync(0xffffffffu, s0, 2);
        s1 += __shfl_xor_sync(0xffffffffu, s1, 1);
        s1 += __shfl_xor_sync(0xffffffffu, s1, 2);
        l0 = l0 * a0 + s0;
        l1 = l1 * a1 + s1;

        #pragma unroll
        for (int nt = 0; nt < 16; nt++) {
            o[nt][0] *= a0; o[nt][1] *= a0;
            o[nt][2] *= a1; o[nt][3] *= a1;
        }

        // ---- O += P_h * (V_hi + V_lo), fp16 2-term ----
        #pragma unroll
        for (int c = 0; c < 4; c++) {
            uint32_t pa0 = pack_h2(sacc[2*c][0],   sacc[2*c][1]);
            uint32_t pa1 = pack_h2(sacc[2*c][2],   sacc[2*c][3]);
            uint32_t pa2 = pack_h2(sacc[2*c+1][0], sacc[2*c+1][1]);
            uint32_t pa3 = pack_h2(sacc[2*c+1][2], sacc[2*c+1][3]);
            #pragma unroll
            for (int dt = 0; dt < 8; dt++) {
                uint32_t vaddr = vs0 + ((c*16 + ((lane>>3)&1)*8 + (lane&7))*ALD
                                        + dt*16 + (lane>>4)*8)*2;
                uint32_t vh0,vh1,vh2,vh3, vl0,vl1,vl2,vl3;
                ldm4t(vh0,vh1,vh2,vh3, vaddr);
                ldm4t(vl0,vl1,vl2,vl3, vaddr + 128*2);
                mma_f16(o[2*dt],   pa0,pa1,pa2,pa3, vh0,vh1);
                mma_f16(o[2*dt],   pa0,pa1,pa2,pa3, vl0,vl1);
                mma_f16(o[2*dt+1], pa0,pa1,pa2,pa3, vh2,vh3);
                mma_f16(o[2*dt+1], pa0,pa1,pa2,pa3, vl2,vl3);
            }
        }
        __syncthreads();
    }

    // ---- normalize + fp16-split write into g_A2 [hi|lo] ----
    const float rn0 = 1.f / l0, rn1 = 1.f / l1;
    const int b = bh >> 4, h = bh & 15;
    const int row0 = q0 + wq + lr;
    const size_t rbase0 = (size_t)(b*S_ + row0) * AK2;
    const size_t rbase1 = (size_t)(b*S_ + row0 + 8) * AK2;
    #pragma unroll
    for (int nt = 0; nt < 16; nt++) {
        int col = h*DH_ + nt*8 + 2*lc;
        uint32_t h0, lo0, h1, lo1;
        split_pack_h(o[nt][0]*rn0, o[nt][1]*rn0, h0, lo0);
        split_pack_h(o[nt][2]*rn1, o[nt][3]*rn1, h1, lo1);
        *(uint32_t*)&g_A2[rbase0 + col]       = h0;
        *(uint32_t*)&g_A2[rbase0 + C_ + col]  = lo0;
        *(uint32_t*)&g_A2[rbase1 + col]       = h1;
        *(uint32_t*)&g_A2[rbase1 + C_ + col]  = lo1;
    }
}

// ---------------------------------------------------------------------------
extern "C" void kernel_launch(void* const* d_in, const int* in_sizes, int n_in,
                              void* d_out, int out_size) {
    const float* x     = (const float*)d_in[0];
    const float* Wqkv  = (const float*)d_in[1];
    const float* Wproj = (const float*)d_in[2];
    float* out = (float*)d_out;

    __half *a2_p, *b2_p;
    cudaGetSymbolAddress((void**)&a2_p, g_A2);
    cudaGetSymbolAddress((void**)&b2_p, g_B2);

    cudaFuncSetAttribute(gemm1_fused,
                         cudaFuncAttributeMaxDynamicSharedMemorySize, GEMM_SMEM);
    cudaFuncSetAttribute(gemm_f16_2term,
                         cudaFuncAttributeMaxDynamicSharedMemorySize, GEMM_SMEM);
    cudaFuncSetAttribute(attn_mma_kernel,
                         cudaFuncAttributeMaxDynamicSharedMemorySize, ATT_SMEM);

    // 1) RoPE sin/cos table
    rope_table_kernel<<<(S_*64 + 255)/256, 256>>>();

    // 2) fp16 split conversions for GEMM1
    conv_A_kernel<<<(B_*S_*C_)/256, 256>>>(x);
    conv_B_kernel<<<dim3((3*C_)/32, C_/32), dim3(32, 8)>>>(Wqkv, 3*C_);

    // 3) fused GEMM1: x @ Wqkv -> RoPE -> split -> g_Q2/K2/V2
    gemm1_fused<<<dim3((3*C_)/GBN, (B_*S_)/GBM), 256, GEMM_SMEM>>>(a2_p, b2_p);

    // 4) tensor-core causal flash attention -> writes fp16-split A2
    attn_mma_kernel<<<dim3(S_/ABR, B_*H_), 256, ATT_SMEM>>>();

    // 5) fp16 split conversion of Wproj
    conv_B_kernel<<<dim3(C_/32, C_/32), dim3(32, 8)>>>(Wproj, C_);

    // 6) out = attn @ Wproj
    gemm_f16_2term<<<dim3(C_/GBN, (B_*S_)/GBM), 256, GEMM_SMEM>>>(
        a2_p, b2_p, out, C_);
}

// round 13
// speedup vs baseline: 1.0240x; 1.0240x over previous
#include <cuda_runtime.h>
#include <cuda_bf16.h>
#include <cuda_fp16.h>
#include <math.h>
#include <stdint.h>

// Problem constants
#define B_   2
#define S_   2048
#define C_   2048
#define H_   16
#define DH_  128
#define QSCALE 0.08838834764831845f

// Scratch (device globals)
__device__ __half g_A2[(size_t)B_*S_*2*C_];      // [4096][4096] = [hi|lo] fp16
__device__ __half g_B2[(size_t)3*C_*2*C_];       // [6144][4096] = [hi|lo] fp16
__device__ __nv_bfloat16 g_Q2[(size_t)B_*H_*S_*256];
__device__ __nv_bfloat16 g_K2[(size_t)B_*H_*S_*256];
__device__ __half        g_V2[(size_t)B_*H_*S_*256];   // fp16 [hi|lo]
__device__ float g_cos[S_*64];
__device__ float g_sin[S_*64];

#define AK2 (2*C_)        // 4096: row stride of A2/B2

__device__ __forceinline__ uint32_t smem_u32(const void* p) {
    uint32_t a;
    asm("{ .reg .u64 t; cvta.to.shared.u64 t, %1; cvt.u32.u64 %0, t; }" : "=r"(a) : "l"(p));
    return a;
}
__device__ __forceinline__ void cp16(uint32_t dst, const void* src) {
    asm volatile("cp.async.cg.shared.global [%0], [%1], 16;" :: "r"(dst), "l"(src));
}
__device__ __forceinline__ void ldm4(uint32_t& r0, uint32_t& r1, uint32_t& r2,
                                     uint32_t& r3, uint32_t addr) {
    asm volatile("ldmatrix.sync.aligned.m8n8.x4.shared.b16 {%0,%1,%2,%3}, [%4];"
        : "=r"(r0), "=r"(r1), "=r"(r2), "=r"(r3) : "r"(addr));
}
__device__ __forceinline__ void ldm4t(uint32_t& r0, uint32_t& r1, uint32_t& r2,
                                      uint32_t& r3, uint32_t addr) {
    asm volatile("ldmatrix.sync.aligned.m8n8.x4.trans.shared.b16 {%0,%1,%2,%3}, [%4];"
        : "=r"(r0), "=r"(r1), "=r"(r2), "=r"(r3) : "r"(addr));
}
__device__ __forceinline__ void mma_bf16(float* c, uint32_t a0, uint32_t a1,
                                         uint32_t a2, uint32_t a3,
                                         uint32_t b0, uint32_t b1) {
    asm volatile("mma.sync.aligned.m16n8k16.row.col.f32.bf16.bf16.f32 "
        "{%0,%1,%2,%3}, {%4,%5,%6,%7}, {%8,%9}, {%0,%1,%2,%3};"
        : "+f"(c[0]), "+f"(c[1]), "+f"(c[2]), "+f"(c[3])
        : "r"(a0), "r"(a1), "r"(a2), "r"(a3), "r"(b0), "r"(b1));
}
__device__ __forceinline__ void mma_f16(float* c, uint32_t a0, uint32_t a1,
                                        uint32_t a2, uint32_t a3,
                                        uint32_t b0, uint32_t b1) {
    asm volatile("mma.sync.aligned.m16n8k16.row.col.f32.f16.f16.f32 "
        "{%0,%1,%2,%3}, {%4,%5,%6,%7}, {%8,%9}, {%0,%1,%2,%3};"
        : "+f"(c[0]), "+f"(c[1]), "+f"(c[2]), "+f"(c[3])
        : "r"(a0), "r"(a1), "r"(a2), "r"(a3), "r"(b0), "r"(b1));
}
__device__ __forceinline__ void split_pack(float x, float y, uint32_t& hi, uint32_t& lo) {
    __nv_bfloat16 hx = __float2bfloat16(x);
    __nv_bfloat16 hy = __float2bfloat16(y);
    __nv_bfloat16 lx = __float2bfloat16(x - __bfloat162float(hx));
    __nv_bfloat16 ly = __float2bfloat16(y - __bfloat162float(hy));
    hi = (uint32_t)*(uint16_t*)&hx | ((uint32_t)*(uint16_t*)&hy << 16);
    lo = (uint32_t)*(uint16_t*)&lx | ((uint32_t)*(uint16_t*)&ly << 16);
}
__device__ __forceinline__ uint32_t pack_h2(float x, float y) {
    __half2 h = __floats2half2_rn(x, y);
    return *(uint32_t*)&h;
}
__device__ __forceinline__ void split_pack_h(float x, float y, uint32_t& hi, uint32_t& lo) {
    __half hx = __float2half(x);
    __half hy = __float2half(y);
    __half lx = __float2half(x - __half2float(hx));
    __half ly = __float2half(y - __half2float(hy));
    hi = (uint32_t)*(uint16_t*)&hx | ((uint32_t)*(uint16_t*)&hy << 16);
    lo = (uint32_t)*(uint16_t*)&lx | ((uint32_t)*(uint16_t*)&ly << 16);
}
__device__ __forceinline__ void split_st(__nv_bfloat16* dst, int off, float v) {
    __nv_bfloat16 hi = __float2bfloat16(v);
    dst[off]       = hi;
    dst[off + 128] = __float2bfloat16(v - __bfloat162float(hi));
}
__device__ __forceinline__ void split_st_h(__half* dst, int off, float v) {
    __half hi = __float2half(v);
    dst[off]       = hi;
    dst[off + 128] = __float2half(v - __half2float(hi));
}

// ---------------------------------------------------------------------------
// RoPE table
// ---------------------------------------------------------------------------
__global__ void rope_table_kernel() {
    int idx = blockIdx.x * blockDim.x + threadIdx.x;
    if (idx >= S_*64) return;
    int s = idx >> 6, d = idx & 63;
    float invf = (float)pow(10000.0, -(double)d / 64.0);
    float ang  = (float)s * invf;
    double a = (double)ang;
    g_cos[idx] = (float)cos(a);
    g_sin[idx] = (float)sin(a);
}

// ---------------------------------------------------------------------------
// fp16 split conversions (vectorized conv_A: 4 elems/thread)
// ---------------------------------------------------------------------------
__global__ void conv_A_kernel(const float* __restrict__ A) {
    int idx = blockIdx.x * blockDim.x + threadIdx.x;   // over elem/4
    int k4 = (idx & ((C_/4)-1)) * 4;
    int m  = idx >> 9;                                  // C_/4 = 512
    float4 v = *(const float4*)(A + (size_t)m * C_ + k4);
    uint32_t h0 = pack_h2(v.x, v.y), h1 = pack_h2(v.z, v.w);
    __half2 hh0 = *(__half2*)&h0, hh1 = *(__half2*)&h1;
    float2 f0 = __half22float2(hh0), f1 = __half22float2(hh1);
    uint32_t l0 = pack_h2(v.x - f0.x, v.y - f0.y);
    uint32_t l1 = pack_h2(v.z - f1.x, v.w - f1.y);
    size_t base = (size_t)m * AK2;
    *(uint2*)&g_A2[base + k4]      = make_uint2(h0, h1);
    *(uint2*)&g_A2[base + C_ + k4] = make_uint2(l0, l1);
}

__global__ void conv_B_kernel(const float* __restrict__ W, int N) {
    __shared__ float tile[32][33];
    int n0 = blockIdx.x * 32, k0 = blockIdx.y * 32;
    int tx = threadIdx.x, ty = threadIdx.y;
    #pragma unroll
    for (int j = 0; j < 4; j++)
        tile[ty + 8*j][tx] = W[(size_t)(k0 + ty + 8*j) * N + n0 + tx];
    __syncthreads();
    #pragma unroll
    for (int j = 0; j < 4; j++) {
        int n = n0 + ty + 8*j;
        int k = k0 + tx;
        float v = tile[tx][ty + 8*j];
        __half hi = __float2half(v);
        __half lo = __float2half(v - __half2float(hi));
        size_t base = (size_t)n * AK2;
        g_B2[base + k]      = hi;
        g_B2[base + C_ + k] = lo;
    }
}

// ---------------------------------------------------------------------------
// GEMM mainloop — EXACT R10 structure (measured best: 507 us on GEMM1).
// fp16 2-term via virtual K=4096, GBK=64, 3-stage, interleaved cp.async,
// LDSM interleaved with MMA groups (B,B then per-mt A+4MMA).
// ---------------------------------------------------------------------------
#define GBM 128
#define GBN 128
#define GBK 64
#define LDT 72
#define OP_ELEMS (128*LDT)
#define NSTG 3
#define GEMM_NT 64                       // 4096/64
#define GEMM_SMEM (NSTG*2*OP_ELEMS*2)    // 110592 B

#define GEMM_MAINLOOP(A_, Bt_)                                                   \
    const int tid  = threadIdx.x;                                                \
    const int lane = tid & 31, wid = tid >> 5;                                   \
    const int wm = wid >> 2, wn = wid & 3;                                       \
    const int bm = blockIdx.y * GBM, bn = blockIdx.x * GBN;                      \
    const uint32_t aBase = smem_u32(gsm);                                        \
    const uint32_t bBase = smem_u32(gsm + NSTG*OP_ELEMS);                        \
    const uint32_t aRowSel = (lane & 15), aColSel = (lane >> 4) * 8;             \
    const uint32_t bRowSel = ((lane >> 4) * 8) + (lane & 7);                     \
    const uint32_t bColSel = ((lane >> 3) & 1) * 8;                              \
    const int rg = tid >> 3, cg8 = (tid & 7) * 8;                                \
    float acc[4][4][4];                                                          \
    _Pragma("unroll")                                                            \
    for (int i = 0; i < 4; i++)                                                  \
        _Pragma("unroll")                                                        \
        for (int j = 0; j < 4; j++)                                              \
            _Pragma("unroll")                                                    \
            for (int r = 0; r < 4; r++) acc[i][j][r] = 0.f;                      \
    auto issue_part = [&](int stg, int kt, int p) {                              \
        const int kv = kt * GBK;                                                 \
        const int koffA = kv & (C_-1);                                           \
        const int koffB = kv;                                                    \
        const uint32_t aD = aBase + stg * OP_ELEMS * 2;                          \
        const uint32_t bD = bBase + stg * OP_ELEMS * 2;                          \
        const int r = rg + p * 32;                                               \
        cp16(aD + (r*LDT + cg8)*2, A_  + (size_t)(bm + r)*AK2 + koffA + cg8);    \
        cp16(bD + (r*LDT + cg8)*2, Bt_ + (size_t)(bn + r)*AK2 + koffB + cg8);    \
    };                                                                           \
    _Pragma("unroll")                                                            \
    for (int p = 0; p < 4; p++) issue_part(0, 0, p);                             \
    asm volatile("cp.async.commit_group;");                                      \
    _Pragma("unroll")                                                            \
    for (int p = 0; p < 4; p++) issue_part(1, 1, p);                             \
    asm volatile("cp.async.commit_group;");                                      \
    for (int kt = 0; kt < GEMM_NT; kt++) {                                       \
        if (kt < GEMM_NT - 1) asm volatile("cp.async.wait_group 1;");            \
        else                  asm volatile("cp.async.wait_group 0;");            \
        __syncthreads();                                                         \
        const bool pf = (kt + 2 < GEMM_NT);                                      \
        const int stg2 = (kt + 2) % NSTG;                                        \
        const uint32_t aS = aBase + (kt % NSTG) * OP_ELEMS * 2;                  \
        const uint32_t bS = bBase + (kt % NSTG) * OP_ELEMS * 2;                  \
        _Pragma("unroll")                                                        \
        for (int kc = 0; kc < 4; kc++) {                                         \
            if (pf) issue_part(stg2, kt + 2, kc);                                \
            uint32_t bf[4][2];                                                   \
            _Pragma("unroll")                                                    \
            for (int np = 0; np < 2; np++) {                                     \
                uint32_t addr = bS + ((wn*32 + np*16 + bRowSel) * LDT            \
                                      + kc*16 + bColSel) * 2;                    \
                uint32_t r0, r1, r2, r3;                                         \
                ldm4(r0, r1, r2, r3, addr);                                      \
                bf[np*2+0][0] = r0; bf[np*2+0][1] = r1;                          \
                bf[np*2+1][0] = r2; bf[np*2+1][1] = r3;                          \
            }                                                                    \
            _Pragma("unroll")                                                    \
            for (int mt = 0; mt < 4; mt++) {                                     \
                uint32_t addr = aS + ((wm*64 + mt*16 + aRowSel) * LDT            \
                                      + kc*16 + aColSel) * 2;                    \
                uint32_t a0, a1, a2, a3;                                         \
                ldm4(a0, a1, a2, a3, addr);                                      \
                _Pragma("unroll")                                                \
                for (int nt = 0; nt < 4; nt++)                                   \
                    mma_f16(acc[mt][nt], a0, a1, a2, a3, bf[nt][0], bf[nt][1]);  \
            }                                                                    \
        }                                                                        \
        if (pf) asm volatile("cp.async.commit_group;");                          \
    }

// ---------------------------------------------------------------------------
// GEMM1 (fused): qkv tile -> RoPE + scale + split -> g_Q2/K2(bf16), g_V2(fp16)
// ---------------------------------------------------------------------------
#define STG_LD 129

__global__ void __launch_bounds__(256, 2) gemm1_fused(
    const __half* __restrict__ A, const __half* __restrict__ Bt)
{
    extern __shared__ __half gsm[];
    GEMM_MAINLOOP(A, Bt)

    __syncthreads();
    float* st = (float*)gsm;                    // 128 x 129 fp32 = 66048 B
    #pragma unroll
    for (int mt = 0; mt < 4; mt++) {
        const int r0 = wm*64 + mt*16 + (lane >> 2);
        #pragma unroll
        for (int nt = 0; nt < 4; nt++) {
            const int col = wn*32 + nt*8 + (lane & 3)*2;
            st[r0*STG_LD + col]       = acc[mt][nt][0];
            st[r0*STG_LD + col + 1]   = acc[mt][nt][1];
            st[(r0+8)*STG_LD + col]   = acc[mt][nt][2];
            st[(r0+8)*STG_LD + col+1] = acc[mt][nt][3];
        }
    }
    __syncthreads();

    const int sec = bn >> 11;                   // 0=K, 1=Q, 2=V
    const int h   = (bn & (C_-1)) >> 7;
    const float scl = (sec == 1) ? QSCALE : 1.f;

    #pragma unroll
    for (int i = 0; i < 32; i++) {
        int p = tid + i*256;
        int r = p >> 6, d = p & 63;
        int grow = bm + r;
        int stok = grow & (S_-1), bb = grow >> 11;
        float t1 = st[r*STG_LD + d], t2 = st[r*STG_LD + d + 64];
        size_t orow = ((size_t)(bb*H_ + h) * S_ + stok) * 256;
        if (sec == 2) {
            split_st_h(g_V2 + orow, d, t1);
            split_st_h(g_V2 + orow, d + 64, t2);
        } else {
            float c  = g_cos[stok*64 + d];
            float sn = g_sin[stok*64 + d];
            float o1 = (t1*c - t2*sn) * scl;
            float o2 = (t2*c + t1*sn) * scl;
            __nv_bfloat16* dstArr = (sec == 0) ? g_K2 : g_Q2;
            split_st(dstArr + orow, d, o1);
            split_st(dstArr + orow, d + 64, o2);
        }
    }
}

// ---------------------------------------------------------------------------
// GEMM2 (plain): writes fp32 C
// ---------------------------------------------------------------------------
__global__ void __launch_bounds__(256, 2) gemm_f16_2term(
    const __half* __restrict__ A, const __half* __restrict__ Bt,
    float* __restrict__ C, int N)
{
    extern __shared__ __half gsm[];
    GEMM_MAINLOOP(A, Bt)

    #pragma unroll
    for (int mt = 0; mt < 4; mt++) {
        const int r0 = bm + wm*64 + mt*16 + (lane >> 2);
        #pragma unroll
        for (int nt = 0; nt < 4; nt++) {
            const int col = bn + wn*32 + nt*8 + (lane & 3)*2;
            *(float2*)(C + (size_t)r0 * N + col) =
                make_float2(acc[mt][nt][0], acc[mt][nt][1]);
            *(float2*)(C + (size_t)(r0 + 8) * N + col) =
                make_float2(acc[mt][nt][2], acc[mt][nt][3]);
        }
    }
}

// ---------------------------------------------------------------------------
// Tensor-core flash attention: QK bf16 3-term, PV fp16 2-term.
// ---------------------------------------------------------------------------
#define ABR 128
#define ABC 64
#define ALD 264
#define QS_ELEMS (ABR*ALD)
#define KV_ELEMS (ABC*ALD)
#define ATT_SMEM ((QS_ELEMS + 4*KV_ELEMS)*2)

__global__ void __launch_bounds__(256, 1) attn_mma_kernel() {
    extern __shared__ __nv_bfloat16 attsm[];
    __nv_bfloat16* Qs = attsm;
    __nv_bfloat16* Ks = attsm + QS_ELEMS;
    __nv_bfloat16* Vs = attsm + QS_ELEMS + 2*KV_ELEMS;   // holds fp16 bits

    const int tid = threadIdx.x, lane = tid & 31, wid = tid >> 5;
    const int qt = gridDim.x - 1 - blockIdx.x;
    const int bh = blockIdx.y;
    const int q0 = qt * ABR;
    const size_t gbase = (size_t)bh * S_ * 256;

    const uint32_t qsB = smem_u32(Qs), ksB = smem_u32(Ks), vsB = smem_u32(Vs);

    {
        const __nv_bfloat16* qsrc = g_Q2 + gbase + (size_t)q0 * 256;
        #pragma unroll
        for (int i = 0; i < 16; i++) {
            int ch = tid + i*256;
            int r = ch >> 5, c8 = (ch & 31) * 8;
            cp16(qsB + (r*ALD + c8)*2, qsrc + (size_t)r*256 + c8);
        }
        const __nv_bfloat16* ksrc = g_K2 + gbase;
        const __half*        vsrc = g_V2 + gbase;
        #pragma unroll
        for (int i = 0; i < 8; i++) {
            int ch = tid + i*256;
            int r = ch >> 5, c8 = (ch & 31) * 8;
            cp16(ksB + (r*ALD + c8)*2, ksrc + (size_t)r*256 + c8);
            cp16(vsB + (r*ALD + c8)*2, vsrc + (size_t)r*256 + c8);
        }
        asm volatile("cp.async.commit_group;");
    }

    const int lr = lane >> 2, lc = lane & 3;
    const int wq = wid * 16;

    float m0 = -1e30f, m1 = -1e30f, l0 = 0.f, l1 = 0.f;
    float o[16][4];
    #pragma unroll
    for (int i = 0; i < 16; i++)
        #pragma unroll
        for (int j = 0; j < 4; j++) o[i][j] = 0.f;

    const int nkb = 2*qt + 2;

    for (int kb = 0; kb < nkb; kb++) {
        const int s = kb & 1;
        if (kb + 1 < nkb) {
            const int ns = s ^ 1;
            const __nv_bfloat16* ksrc = g_K2 + gbase + (size_t)((kb+1)*ABC) * 256;
            const __half*        vsrc = g_V2 + gbase + (size_t)((kb+1)*ABC) * 256;
            uint32_t kd = ksB + ns*KV_ELEMS*2, vd = vsB + ns*KV_ELEMS*2;
            #pragma unroll
            for (int i = 0; i < 8; i++) {
                int ch = tid + i*256;
                int r = ch >> 5, c8 = (ch & 31) * 8;
                cp16(kd + (r*ALD + c8)*2, ksrc + (size_t)r*256 + c8);
                cp16(vd + (r*ALD + c8)*2, vsrc + (size_t)r*256 + c8);
            }
            asm volatile("cp.async.commit_group;");
            asm volatile("cp.async.wait_group 1;");
        } else {
            asm volatile("cp.async.wait_group 0;");
        }
        __syncthreads();

        const uint32_t ks0 = ksB + s*KV_ELEMS*2;
        const uint32_t vs0 = vsB + s*KV_ELEMS*2;

        float sacc[8][4];
        #pragma unroll
        for (int i = 0; i < 8; i++)
            #pragma unroll
            for (int j = 0; j < 4; j++) sacc[i][j] = 0.f;

        #pragma unroll
        for (int kc = 0; kc < 8; kc++) {
            uint32_t qaddr = qsB + ((wq + (lane & 15))*ALD + kc*16 + (lane >> 4)*8)*2;
            uint32_t qh0,qh1,qh2,qh3, ql0,ql1,ql2,ql3;
            ldm4(qh0,qh1,qh2,qh3, qaddr);
            ldm4(ql0,ql1,ql2,ql3, qaddr + 128*2);
            #pragma unroll
            for (int ntp = 0; ntp < 4; ntp++) {
                uint32_t baddr = ks0 + ((ntp*16 + (lane>>4)*8 + (lane&7))*ALD
                                        + kc*16 + ((lane>>3)&1)*8)*2;
                uint32_t h0,h1,h2,h3, e0,e1,e2,e3;
                ldm4(h0,h1,h2,h3, baddr);
                ldm4(e0,e1,e2,e3, baddr + 128*2);
                mma_bf16(sacc[2*ntp],   qh0,qh1,qh2,qh3, h0,h1);
                mma_bf16(sacc[2*ntp],   qh0,qh1,qh2,qh3, e0,e1);
                mma_bf16(sacc[2*ntp],   ql0,ql1,ql2,ql3, h0,h1);
                mma_bf16(sacc[2*ntp+1], qh0,qh1,qh2,qh3, h2,h3);
                mma_bf16(sacc[2*ntp+1], qh0,qh1,qh2,qh3, e2,e3);
                mma_bf16(sacc[2*ntp+1], ql0,ql1,ql2,ql3, h2,h3);
            }
        }

        const int r0 = q0 + wq + lr, r1 = r0 + 8;
        if (kb >= 2*qt) {
            #pragma unroll
            for (int nt = 0; nt < 8; nt++) {
                int key = kb*ABC + nt*8 + 2*lc;
                if (key     > r0) sacc[nt][0] = -1e30f;
                if (key + 1 > r0) sacc[nt][1] = -1e30f;
                if (key     > r1) sacc[nt][2] = -1e30f;
                if (key + 1 > r1) sacc[nt][3] = -1e30f;
            }
        }

        float mx0 = m0, mx1 = m1;
        #pragma unroll
        for (int nt = 0; nt < 8; nt++) {
            mx0 = fmaxf(mx0, fmaxf(sacc[nt][0], sacc[nt][1]));
            mx1 = fmaxf(mx1, fmaxf(sacc[nt][2], sacc[nt][3]));
        }
        mx0 = fmaxf(mx0, __shfl_xor_sync(0xffffffffu, mx0, 1));
        mx0 = fmaxf(mx0, __shfl_xor_sync(0xffffffffu, mx0, 2));
        mx1 = fmaxf(mx1, __shfl_xor_sync(0xffffffffu, mx1, 1));
        mx1 = fmaxf(mx1, __shfl_xor_sync(0xffffffffu, mx1, 2));
        float a0 = __expf(m0 - mx0), a1 = __expf(m1 - mx1);
        m0 = mx0; m1 = mx1;

        float s0 = 0.f, s1 = 0.f;
        #pragma unroll
        for (int nt = 0; nt < 8; nt++) {
            sacc[nt][0] = __expf(sacc[nt][0] - m0); s0 += sacc[nt][0];
            sacc[nt][1] = __expf(sacc[nt][1] - m0); s0 += sacc[nt][1];
            sacc[nt][2] = __expf(sacc[nt][2] - m1); s1 += sacc[nt][2];
            sacc[nt][3] = __expf(sacc[nt][3] - m1); s1 += sacc[nt][3];
        }
        s0 += __shfl_xor_sync(0xffffffffu, s0, 1);
        s0 += __shfl_xor_sync(0xffffffffu, s0, 2);
        s1 += __shfl_xor_sync(0xffffffffu, s1, 1);
        s1 += __shfl_xor_sync(0xffffffffu, s1, 2);
        l0 = l0 * a0 + s0;
        l1 = l1 * a1 + s1;

        #pragma unroll
        for (int nt = 0; nt < 16; nt++) {
            o[nt][0] *= a0; o[nt][1] *= a0;
            o[nt][2] *= a1; o[nt][3] *= a1;
        }

        // ---- O += P_h * (V_hi + V_lo), fp16 2-term ----
        #pragma unroll
        for (int c = 0; c < 4; c++) {
            uint32_t pa0 = pack_h2(sacc[2*c][0],   sacc[2*c][1]);
            uint32_t pa1 = pack_h2(sacc[2*c][2],   sacc[2*c][3]);
            uint32_t pa2 = pack_h2(sacc[2*c+1][0], sacc[2*c+1][1]);
            uint32_t pa3 = pack_h2(sacc[2*c+1][2], sacc[2*c+1][3]);
            #pragma unroll
            for (int dt = 0; dt < 8; dt++) {
                uint32_t vaddr = vs0 + ((c*16 + ((lane>>3)&1)*8 + (lane&7))*ALD
                                        + dt*16 + (lane>>4)*8)*2;
                uint32_t vh0,vh1,vh2,vh3, vl0,vl1,vl2,vl3;
                ldm4t(vh0,vh1,vh2,vh3, vaddr);
                ldm4t(vl0,vl1,vl2,vl3, vaddr + 128*2);
                mma_f16(o[2*dt],   pa0,pa1,pa2,pa3, vh0,vh1);
                mma_f16(o[2*dt],   pa0,pa1,pa2,pa3, vl0,vl1);
                mma_f16(o[2*dt+1], pa0,pa1,pa2,pa3, vh2,vh3);
                mma_f16(o[2*dt+1], pa0,pa1,pa2,pa3, vl2,vl3);
            }
        }
        __syncthreads();
    }

    // ---- normalize + fp16-split write into g_A2 [hi|lo] ----
    const float rn0 = 1.f / l0, rn1 = 1.f / l1;
    const int b = bh >> 4, h = bh & 15;
    const int row0 = q0 + wq + lr;
    const size_t rbase0 = (size_t)(b*S_ + row0) * AK2;
    const size_t rbase1 = (size_t)(b*S_ + row0 + 8) * AK2;
    #pragma unroll
    for (int nt = 0; nt < 16; nt++) {
        int col = h*DH_ + nt*8 + 2*lc;
        uint32_t h0, lo0, h1, lo1;
        split_pack_h(o[nt][0]*rn0, o[nt][1]*rn0, h0, lo0);
        split_pack_h(o[nt][2]*rn1, o[nt][3]*rn1, h1, lo1);
        *(uint32_t*)&g_A2[rbase0 + col]       = h0;
        *(uint32_t*)&g_A2[rbase0 + C_ + col]  = lo0;
        *(uint32_t*)&g_A2[rbase1 + col]       = h1;
        *(uint32_t*)&g_A2[rbase1 + C_ + col]  = lo1;
    }
}

// ---------------------------------------------------------------------------
extern "C" void kernel_launch(void* const* d_in, const int* in_sizes, int n_in,
                              void* d_out, int out_size) {
    const float* x     = (const float*)d_in[0];
    const float* Wqkv  = (const float*)d_in[1];
    const float* Wproj = (const float*)d_in[2];
    float* out = (float*)d_out;

    __half *a2_p, *b2_p;
    cudaGetSymbolAddress((void**)&a2_p, g_A2);
    cudaGetSymbolAddress((void**)&b2_p, g_B2);

    cudaFuncSetAttribute(gemm1_fused,
                         cudaFuncAttributeMaxDynamicSharedMemorySize, GEMM_SMEM);
    cudaFuncSetAttribute(gemm_f16_2term,
                         cudaFuncAttributeMaxDynamicSharedMemorySize, GEMM_SMEM);
    cudaFuncSetAttribute(attn_mma_kernel,
                         cudaFuncAttributeMaxDynamicSharedMemorySize, ATT_SMEM);

    // 1) RoPE sin/cos table
    rope_table_kernel<<<(S_*64 + 255)/256, 256>>>();

    // 2) fp16 split conversions for GEMM1
    conv_A_kernel<<<(B_*S_*C_/4)/256, 256>>>(x);
    conv_B_kernel<<<dim3((3*C_)/32, C_/32), dim3(32, 8)>>>(Wqkv, 3*C_);

    // 3) fused GEMM1: x @ Wqkv -> RoPE -> split -> g_Q2/K2/V2
    gemm1_fused<<<dim3((3*C_)/GBN, (B_*S_)/GBM), 256, GEMM_SMEM>>>(a2_p, b2_p);

    // 4) tensor-core causal flash attention -> writes fp16-split A2
    attn_mma_kernel<<<dim3(S_/ABR, B_*H_), 256, ATT_SMEM>>>();

    // 5) fp16 split conversion of Wproj
    conv_B_kernel<<<dim3(C_/32, C_/32), dim3(32, 8)>>>(Wproj, C_);

    // 6) out = attn @ Wproj
    gemm_f16_2term<<<dim3(C_/GBN, (B_*S_)/GBM), 256, GEMM_SMEM>>>(
        a2_p, b2_p, out, C_);
}

// round 15
// speedup vs baseline: 1.0599x; 1.0351x over previous
#include <cuda_runtime.h>
#include <cuda_bf16.h>
#include <cuda_fp16.h>
#include <math.h>
#include <stdint.h>

// Problem constants
#define B_   2
#define S_   2048
#define C_   2048
#define H_   16
#define DH_  128
// Dh^-0.5 * log2(e): softmax via exp2
#define QSCALE (0.08838834764831845f * 1.4426950408889634f)

// Scratch (device globals)
__device__ __half g_A2[(size_t)B_*S_*2*C_];      // [4096][4096] = [hi|lo] fp16
__device__ __half g_B2[(size_t)3*C_*2*C_];       // [6144][4096] Wqkv^T [hi|lo]
__device__ __half g_B2p[(size_t)C_*2*C_];        // [2048][4096] Wproj^T [hi|lo]
__device__ __nv_bfloat16 g_Q2[(size_t)B_*H_*S_*256];
__device__ __nv_bfloat16 g_K2[(size_t)B_*H_*S_*256];
__device__ __half        g_V2[(size_t)B_*H_*S_*256];   // fp16 [hi|lo]
__device__ float g_cos[S_*64];
__device__ float g_sin[S_*64];

#define AK2 (2*C_)        // 4096: row stride of A2/B2/B2p

__device__ __forceinline__ uint32_t smem_u32(const void* p) {
    uint32_t a;
    asm("{ .reg .u64 t; cvta.to.shared.u64 t, %1; cvt.u32.u64 %0, t; }" : "=r"(a) : "l"(p));
    return a;
}
__device__ __forceinline__ void cp16(uint32_t dst, const void* src) {
    asm volatile("cp.async.cg.shared.global [%0], [%1], 16;" :: "r"(dst), "l"(src));
}
__device__ __forceinline__ void ldm4(uint32_t& r0, uint32_t& r1, uint32_t& r2,
                                     uint32_t& r3, uint32_t addr) {
    asm volatile("ldmatrix.sync.aligned.m8n8.x4.shared.b16 {%0,%1,%2,%3}, [%4];"
        : "=r"(r0), "=r"(r1), "=r"(r2), "=r"(r3) : "r"(addr));
}
__device__ __forceinline__ void ldm4t(uint32_t& r0, uint32_t& r1, uint32_t& r2,
                                      uint32_t& r3, uint32_t addr) {
    asm volatile("ldmatrix.sync.aligned.m8n8.x4.trans.shared.b16 {%0,%1,%2,%3}, [%4];"
        : "=r"(r0), "=r"(r1), "=r"(r2), "=r"(r3) : "r"(addr));
}
__device__ __forceinline__ void mma_bf16(float* c, uint32_t a0, uint32_t a1,
                                         uint32_t a2, uint32_t a3,
                                         uint32_t b0, uint32_t b1) {
    asm volatile("mma.sync.aligned.m16n8k16.row.col.f32.bf16.bf16.f32 "
        "{%0,%1,%2,%3}, {%4,%5,%6,%7}, {%8,%9}, {%0,%1,%2,%3};"
        : "+f"(c[0]), "+f"(c[1]), "+f"(c[2]), "+f"(c[3])
        : "r"(a0), "r"(a1), "r"(a2), "r"(a3), "r"(b0), "r"(b1));
}
__device__ __forceinline__ void mma_f16(float* c, uint32_t a0, uint32_t a1,
                                        uint32_t a2, uint32_t a3,
                                        uint32_t b0, uint32_t b1) {
    asm volatile("mma.sync.aligned.m16n8k16.row.col.f32.f16.f16.f32 "
        "{%0,%1,%2,%3}, {%4,%5,%6,%7}, {%8,%9}, {%0,%1,%2,%3};"
        : "+f"(c[0]), "+f"(c[1]), "+f"(c[2]), "+f"(c[3])
        : "r"(a0), "r"(a1), "r"(a2), "r"(a3), "r"(b0), "r"(b1));
}
__device__ __forceinline__ float fexp2(float x) {
    float r;
    asm("ex2.approx.ftz.f32 %0, %1;" : "=f"(r) : "f"(x));
    return r;
}
__device__ __forceinline__ void split_pack(float x, float y, uint32_t& hi, uint32_t& lo) {
    __nv_bfloat16 hx = __float2bfloat16(x);
    __nv_bfloat16 hy = __float2bfloat16(y);
    __nv_bfloat16 lx = __float2bfloat16(x - __bfloat162float(hx));
    __nv_bfloat16 ly = __float2bfloat16(y - __bfloat162float(hy));
    hi = (uint32_t)*(uint16_t*)&hx | ((uint32_t)*(uint16_t*)&hy << 16);
    lo = (uint32_t)*(uint16_t*)&lx | ((uint32_t)*(uint16_t*)&ly << 16);
}
__device__ __forceinline__ uint32_t pack_h2(float x, float y) {
    __half2 h = __floats2half2_rn(x, y);
    return *(uint32_t*)&h;
}
__device__ __forceinline__ void split_pack_h(float x, float y, uint32_t& hi, uint32_t& lo) {
    __half hx = __float2half(x);
    __half hy = __float2half(y);
    __half lx = __float2half(x - __half2float(hx));
    __half ly = __float2half(y - __half2float(hy));
    hi = (uint32_t)*(uint16_t*)&hx | ((uint32_t)*(uint16_t*)&hy << 16);
    lo = (uint32_t)*(uint16_t*)&lx | ((uint32_t)*(uint16_t*)&ly << 16);
}
__device__ __forceinline__ void split_st(__nv_bfloat16* dst, int off, float v) {
    __nv_bfloat16 hi = __float2bfloat16(v);
    dst[off]       = hi;
    dst[off + 128] = __float2bfloat16(v - __bfloat162float(hi));
}
__device__ __forceinline__ void split_st_h(__half* dst, int off, float v) {
    __half hi = __float2half(v);
    dst[off]       = hi;
    dst[off + 128] = __float2half(v - __half2float(hi));
}

// ---------------------------------------------------------------------------
// Mega-prep: rope table + conv_A + conv_B(Wqkv->g_B2) + conv_B(Wproj->g_B2p)
// ---------------------------------------------------------------------------
#define PREP_ROPE_BLKS  512
#define PREP_CONVA_BLKS 8192
#define PREP_CBQ_BLKS   12288      // (6144/32)*(2048/32)
#define PREP_CBP_BLKS   4096       // (2048/32)*(2048/32)
#define PREP_BLKS (PREP_ROPE_BLKS + PREP_CONVA_BLKS + PREP_CBQ_BLKS + PREP_CBP_BLKS)

__device__ __forceinline__ void conv_B_body(const float* __restrict__ W, int N,
                                            __half* __restrict__ dst,
                                            int n0, int k0, int tid,
                                            float (*tile)[33]) {
    int tx = tid & 31, ty = tid >> 5;
    #pragma unroll
    for (int j = 0; j < 4; j++)
        tile[ty + 8*j][tx] = W[(size_t)(k0 + ty + 8*j) * N + n0 + tx];
    __syncthreads();
    #pragma unroll
    for (int j = 0; j < 4; j++) {
        int n = n0 + ty + 8*j;
        int k = k0 + tx;
        float v = tile[tx][ty + 8*j];
        __half hi = __float2half(v);
        __half lo = __float2half(v - __half2float(hi));
        size_t base = (size_t)n * AK2;
        dst[base + k]      = hi;
        dst[base + C_ + k] = lo;
    }
}

__global__ void __launch_bounds__(256) prep_kernel(
    const float* __restrict__ x,
    const float* __restrict__ Wqkv,
    const float* __restrict__ Wproj)
{
    __shared__ float tile[32][33];
    const int bx = blockIdx.x, tid = threadIdx.x;

    if (bx < PREP_ROPE_BLKS) {
        int idx = bx * 256 + tid;
        int s = idx >> 6, d = idx & 63;
        float invf = (float)pow(10000.0, -(double)d / 64.0);
        float ang  = (float)s * invf;
        double a = (double)ang;
        g_cos[idx] = (float)cos(a);
        g_sin[idx] = (float)sin(a);
    } else if (bx < PREP_ROPE_BLKS + PREP_CONVA_BLKS) {
        int idx = (bx - PREP_ROPE_BLKS) * 256 + tid;
        int k4 = (idx & ((C_/4)-1)) * 4;
        int m  = idx >> 9;
        float4 v = *(const float4*)(x + (size_t)m * C_ + k4);
        uint32_t h0 = pack_h2(v.x, v.y), h1 = pack_h2(v.z, v.w);
        __half2 hh0 = *(__half2*)&h0, hh1 = *(__half2*)&h1;
        float2 f0 = __half22float2(hh0), f1 = __half22float2(hh1);
        uint32_t l0 = pack_h2(v.x - f0.x, v.y - f0.y);
        uint32_t l1 = pack_h2(v.z - f1.x, v.w - f1.y);
        size_t base = (size_t)m * AK2;
        *(uint2*)&g_A2[base + k4]      = make_uint2(h0, h1);
        *(uint2*)&g_A2[base + C_ + k4] = make_uint2(l0, l1);
    } else if (bx < PREP_ROPE_BLKS + PREP_CONVA_BLKS + PREP_CBQ_BLKS) {
        int bid = bx - (PREP_ROPE_BLKS + PREP_CONVA_BLKS);
        int n0 = (bid % 192) * 32, k0 = (bid / 192) * 32;
        conv_B_body(Wqkv, 3*C_, g_B2, n0, k0, tid, tile);
    } else {
        int bid = bx - (PREP_ROPE_BLKS + PREP_CONVA_BLKS + PREP_CBQ_BLKS);
        int n0 = (bid & 63) * 32, k0 = (bid >> 6) * 32;
        conv_B_body(Wproj, C_, g_B2p, n0, k0, tid, tile);
    }
}

// ---------------------------------------------------------------------------
// GEMM mainloop — EXACT R10/R13 structure (measured best).
// ---------------------------------------------------------------------------
#define GBM 128
#define GBN 128
#define GBK 64
#define LDT 72
#define OP_ELEMS (128*LDT)
#define NSTG 3
#define GEMM_NT 64                       // 4096/64
#define GEMM_SMEM (NSTG*2*OP_ELEMS*2)    // 110592 B

#define GEMM_MAINLOOP(A_, Bt_)                                                   \
    const int tid  = threadIdx.x;                                                \
    const int lane = tid & 31, wid = tid >> 5;                                   \
    const int wm = wid >> 2, wn = wid & 3;                                       \
    const int bm = blockIdx.y * GBM, bn = blockIdx.x * GBN;                      \
    const uint32_t aBase = smem_u32(gsm);                                        \
    const uint32_t bBase = smem_u32(gsm + NSTG*OP_ELEMS);                        \
    const uint32_t aRowSel = (lane & 15), aColSel = (lane >> 4) * 8;             \
    const uint32_t bRowSel = ((lane >> 4) * 8) + (lane & 7);                     \
    const uint32_t bColSel = ((lane >> 3) & 1) * 8;                              \
    const int rg = tid >> 3, cg8 = (tid & 7) * 8;                                \
    float acc[4][4][4];                                                          \
    _Pragma("unroll")                                                            \
    for (int i = 0; i < 4; i++)                                                  \
        _Pragma("unroll")                                                        \
        for (int j = 0; j < 4; j++)                                              \
            _Pragma("unroll")                                                    \
            for (int r = 0; r < 4; r++) acc[i][j][r] = 0.f;                      \
    auto issue_part = [&](int stg, int kt, int p) {                              \
        const int kv = kt * GBK;                                                 \
        const int koffA = kv & (C_-1);                                           \
        const int koffB = kv;                                                    \
        const uint32_t aD = aBase + stg * OP_ELEMS * 2;                          \
        const uint32_t bD = bBase + stg * OP_ELEMS * 2;                          \
        const int r = rg + p * 32;                                               \
        cp16(aD + (r*LDT + cg8)*2, A_  + (size_t)(bm + r)*AK2 + koffA + cg8);    \
        cp16(bD + (r*LDT + cg8)*2, Bt_ + (size_t)(bn + r)*AK2 + koffB + cg8);    \
    };                                                                           \
    _Pragma("unroll")                                                            \
    for (int p = 0; p < 4; p++) issue_part(0, 0, p);                             \
    asm volatile("cp.async.commit_group;");                                      \
    _Pragma("unroll")                                                            \
    for (int p = 0; p < 4; p++) issue_part(1, 1, p);                             \
    asm volatile("cp.async.commit_group;");                                      \
    for (int kt = 0; kt < GEMM_NT; kt++) {                                       \
        if (kt < GEMM_NT - 1) asm volatile("cp.async.wait_group 1;");            \
        else                  asm volatile("cp.async.wait_group 0;");            \
        __syncthreads();                                                         \
        const bool pf = (kt + 2 < GEMM_NT);                                      \
        const int stg2 = (kt + 2) % NSTG;                                        \
        const uint32_t aS = aBase + (kt % NSTG) * OP_ELEMS * 2;                  \
        const uint32_t bS = bBase + (kt % NSTG) * OP_ELEMS * 2;                  \
        _Pragma("unroll")                                                        \
        for (int kc = 0; kc < 4; kc++) {                                         \
            if (pf) issue_part(stg2, kt + 2, kc);                                \
            uint32_t bf[4][2];                                                   \
            _Pragma("unroll")                                                    \
            for (int np = 0; np < 2; np++) {                                     \
                uint32_t addr = bS + ((wn*32 + np*16 + bRowSel) * LDT            \
                                      + kc*16 + bColSel) * 2;                    \
                uint32_t r0, r1, r2, r3;                                         \
                ldm4(r0, r1, r2, r3, addr);                                      \
                bf[np*2+0][0] = r0; bf[np*2+0][1] = r1;                          \
                bf[np*2+1][0] = r2; bf[np*2+1][1] = r3;                          \
            }                                                                    \
            _Pragma("unroll")                                                    \
            for (int mt = 0; mt < 4; mt++) {                                     \
                uint32_t addr = aS + ((wm*64 + mt*16 + aRowSel) * LDT            \
                                      + kc*16 + aColSel) * 2;                    \
                uint32_t a0, a1, a2, a3;                                         \
                ldm4(a0, a1, a2, a3, addr);                                      \
                _Pragma("unroll")                                                \
                for (int nt = 0; nt < 4; nt++)                                   \
                    mma_f16(acc[mt][nt], a0, a1, a2, a3, bf[nt][0], bf[nt][1]);  \
            }                                                                    \
        }                                                                        \
        if (pf) asm volatile("cp.async.commit_group;");                          \
    }

// ---------------------------------------------------------------------------
// GEMM1 (fused): qkv tile -> RoPE + scale + split -> g_Q2/K2(bf16), g_V2(fp16)
// ---------------------------------------------------------------------------
#define STG_LD 129

__global__ void __launch_bounds__(256, 2) gemm1_fused(
    const __half* __restrict__ A, const __half* __restrict__ Bt)
{
    extern __shared__ __half gsm[];
    GEMM_MAINLOOP(A, Bt)

    __syncthreads();
    float* st = (float*)gsm;                    // 128 x 129 fp32 = 66048 B
    #pragma unroll
    for (int mt = 0; mt < 4; mt++) {
        const int r0 = wm*64 + mt*16 + (lane >> 2);
        #pragma unroll
        for (int nt = 0; nt < 4; nt++) {
            const int col = wn*32 + nt*8 + (lane & 3)*2;
            st[r0*STG_LD + col]       = acc[mt][nt][0];
            st[r0*STG_LD + col + 1]   = acc[mt][nt][1];
            st[(r0+8)*STG_LD + col]   = acc[mt][nt][2];
            st[(r0+8)*STG_LD + col+1] = acc[mt][nt][3];
        }
    }
    __syncthreads();

    const int sec = bn >> 11;                   // 0=K, 1=Q, 2=V
    const int h   = (bn & (C_-1)) >> 7;
    const float scl = (sec == 1) ? QSCALE : 1.f;

    #pragma unroll
    for (int i = 0; i < 32; i++) {
        int p = tid + i*256;
        int r = p >> 6, d = p & 63;
        int grow = bm + r;
        int stok = grow & (S_-1), bb = grow >> 11;
        float t1 = st[r*STG_LD + d], t2 = st[r*STG_LD + d + 64];
        size_t orow = ((size_t)(bb*H_ + h) * S_ + stok) * 256;
        if (sec == 2) {
            split_st_h(g_V2 + orow, d, t1);
            split_st_h(g_V2 + orow, d + 64, t2);
        } else {
            float c  = g_cos[stok*64 + d];
            float sn = g_sin[stok*64 + d];
            float o1 = (t1*c - t2*sn) * scl;
            float o2 = (t2*c + t1*sn) * scl;
            __nv_bfloat16* dstArr = (sec == 0) ? g_K2 : g_Q2;
            split_st(dstArr + orow, d, o1);
            split_st(dstArr + orow, d + 64, o2);
        }
    }
}

// ---------------------------------------------------------------------------
// GEMM2 (plain): writes fp32 C
// ---------------------------------------------------------------------------
__global__ void __launch_bounds__(256, 2) gemm_f16_2term(
    const __half* __restrict__ A, const __half* __restrict__ Bt,
    float* __restrict__ C, int N)
{
    extern __shared__ __half gsm[];
    GEMM_MAINLOOP(A, Bt)

    #pragma unroll
    for (int mt = 0; mt < 4; mt++) {
        const int r0 = bm + wm*64 + mt*16 + (lane >> 2);
        #pragma unroll
        for (int nt = 0; nt < 4; nt++) {
            const int col = bn + wn*32 + nt*8 + (lane & 3)*2;
            *(float2*)(C + (size_t)r0 * N + col) =
                make_float2(acc[mt][nt][0], acc[mt][nt][1]);
            *(float2*)(C + (size_t)(r0 + 8) * N + col) =
                make_float2(acc[mt][nt][2], acc[mt][nt][3]);
        }
    }
}

// ---------------------------------------------------------------------------
// Tensor-core flash attention: QK bf16 3-term, PV fp16 2-term, exp2 softmax.
// ---------------------------------------------------------------------------
#define ABR 128
#define ABC 64
#define ALD 264
#define QS_ELEMS (ABR*ALD)
#define KV_ELEMS (ABC*ALD)
#define ATT_SMEM ((QS_ELEMS + 4*KV_ELEMS)*2)

__global__ void __launch_bounds__(256, 1) attn_mma_kernel() {
    extern __shared__ __nv_bfloat16 attsm[];
    __nv_bfloat16* Qs = attsm;
    __nv_bfloat16* Ks = attsm + QS_ELEMS;
    __nv_bfloat16* Vs = attsm + QS_ELEMS + 2*KV_ELEMS;   // holds fp16 bits

    const int tid = threadIdx.x, lane = tid & 31, wid = tid >> 5;
    const int qt = gridDim.x - 1 - blockIdx.x;
    const int bh = blockIdx.y;
    const int q0 = qt * ABR;
    const size_t gbase = (size_t)bh * S_ * 256;

    const uint32_t qsB = smem_u32(Qs), ksB = smem_u32(Ks), vsB = smem_u32(Vs);

    {
        const __nv_bfloat16* qsrc = g_Q2 + gbase + (size_t)q0 * 256;
        #pragma unroll
        for (int i = 0; i < 16; i++) {
            int ch = tid + i*256;
            int r = ch >> 5, c8 = (ch & 31) * 8;
            cp16(qsB + (r*ALD + c8)*2, qsrc + (size_t)r*256 + c8);
        }
        const __nv_bfloat16* ksrc = g_K2 + gbase;
        const __half*        vsrc = g_V2 + gbase;
        #pragma unroll
        for (int i = 0; i < 8; i++) {
            int ch = tid + i*256;
            int r = ch >> 5, c8 = (ch & 31) * 8;
            cp16(ksB + (r*ALD + c8)*2, ksrc + (size_t)r*256 + c8);
            cp16(vsB + (r*ALD + c8)*2, vsrc + (size_t)r*256 + c8);
        }
        asm volatile("cp.async.commit_group;");
    }

    const int lr = lane >> 2, lc = lane & 3;
    const int wq = wid * 16;

    float m0 = -1e30f, m1 = -1e30f, l0 = 0.f, l1 = 0.f;
    float o[16][4];
    #pragma unroll
    for (int i = 0; i < 16; i++)
        #pragma unroll
        for (int j = 0; j < 4; j++) o[i][j] = 0.f;

    const int nkb = 2*qt + 2;

    for (int kb = 0; kb < nkb; kb++) {
        const int s = kb & 1;
        if (kb + 1 < nkb) {
            const int ns = s ^ 1;
            const __nv_bfloat16* ksrc = g_K2 + gbase + (size_t)((kb+1)*ABC) * 256;
            const __half*        vsrc = g_V2 + gbase + (size_t)((kb+1)*ABC) * 256;
            uint32_t kd = ksB + ns*KV_ELEMS*2, vd = vsB + ns*KV_ELEMS*2;
            #pragma unroll
            for (int i = 0; i < 8; i++) {
                int ch = tid + i*256;
                int r = ch >> 5, c8 = (ch & 31) * 8;
                cp16(kd + (r*ALD + c8)*2, ksrc + (size_t)r*256 + c8);
                cp16(vd + (r*ALD + c8)*2, vsrc + (size_t)r*256 + c8);
            }
            asm volatile("cp.async.commit_group;");
            asm volatile("cp.async.wait_group 1;");
        } else {
            asm volatile("cp.async.wait_group 0;");
        }
        __syncthreads();

        const uint32_t ks0 = ksB + s*KV_ELEMS*2;
        const uint32_t vs0 = vsB + s*KV_ELEMS*2;

        float sacc[8][4];
        #pragma unroll
        for (int i = 0; i < 8; i++)
            #pragma unroll
            for (int j = 0; j < 4; j++) sacc[i][j] = 0.f;

        #pragma unroll
        for (int kc = 0; kc < 8; kc++) {
            uint32_t qaddr = qsB + ((wq + (lane & 15))*ALD + kc*16 + (lane >> 4)*8)*2;
            uint32_t qh0,qh1,qh2,qh3, ql0,ql1,ql2,ql3;
            ldm4(qh0,qh1,qh2,qh3, qaddr);
            ldm4(ql0,ql1,ql2,ql3, qaddr + 128*2);
            #pragma unroll
            for (int ntp = 0; ntp < 4; ntp++) {
                uint32_t baddr = ks0 + ((ntp*16 + (lane>>4)*8 + (lane&7))*ALD
                                        + kc*16 + ((lane>>3)&1)*8)*2;
                uint32_t h0,h1,h2,h3, e0,e1,e2,e3;
                ldm4(h0,h1,h2,h3, baddr);
                ldm4(e0,e1,e2,e3, baddr + 128*2);
                mma_bf16(sacc[2*ntp],   qh0,qh1,qh2,qh3, h0,h1);
                mma_bf16(sacc[2*ntp],   qh0,qh1,qh2,qh3, e0,e1);
                mma_bf16(sacc[2*ntp],   ql0,ql1,ql2,ql3, h0,h1);
                mma_bf16(sacc[2*ntp+1], qh0,qh1,qh2,qh3, h2,h3);
                mma_bf16(sacc[2*ntp+1], qh0,qh1,qh2,qh3, e2,e3);
                mma_bf16(sacc[2*ntp+1], ql0,ql1,ql2,ql3, h2,h3);
            }
        }

        const int r0 = q0 + wq + lr, r1 = r0 + 8;
        if (kb >= 2*qt) {
            #pragma unroll
            for (int nt = 0; nt < 8; nt++) {
                int key = kb*ABC + nt*8 + 2*lc;
                if (key     > r0) sacc[nt][0] = -1e30f;
                if (key + 1 > r0) sacc[nt][1] = -1e30f;
                if (key     > r1) sacc[nt][2] = -1e30f;
                if (key + 1 > r1) sacc[nt][3] = -1e30f;
            }
        }

        float mx0 = m0, mx1 = m1;
        #pragma unroll
        for (int nt = 0; nt < 8; nt++) {
            mx0 = fmaxf(mx0, fmaxf(sacc[nt][0], sacc[nt][1]));
            mx1 = fmaxf(mx1, fmaxf(sacc[nt][2], sacc[nt][3]));
        }
        mx0 = fmaxf(mx0, __shfl_xor_sync(0xffffffffu, mx0, 1));
        mx0 = fmaxf(mx0, __shfl_xor_sync(0xffffffffu, mx0, 2));
        mx1 = fmaxf(mx1, __shfl_xor_sync(0xffffffffu, mx1, 1));
        mx1 = fmaxf(mx1, __shfl_xor_sync(0xffffffffu, mx1, 2));
        float a0 = fexp2(m0 - mx0), a1 = fexp2(m1 - mx1);
        m0 = mx0; m1 = mx1;

        float s0 = 0.f, s1 = 0.f;
        #pragma unroll
        for (int nt = 0; nt < 8; nt++) {
            sacc[nt][0] = fexp2(sacc[nt][0] - m0); s0 += sacc[nt][0];
            sacc[nt][1] = fexp2(sacc[nt][1] - m0); s0 += sacc[nt][1];
            sacc[nt][2] = fexp2(sacc[nt][2] - m1); s1 += sacc[nt][2];
            sacc[nt][3] = fexp2(sacc[nt][3] - m1); s1 += sacc[nt][3];
        }
        s0 += __shfl_xor_sync(0xffffffffu, s0, 1);
        s0 += __shfl_xor_sync(0xffffffffu, s0, 2);
        s1 += __shfl_xor_sync(0xffffffffu, s1, 1);
        s1 += __shfl_xor_sync(0xffffffffu, s1, 2);
        l0 = l0 * a0 + s0;
        l1 = l1 * a1 + s1;

        #pragma unroll
        for (int nt = 0; nt < 16; nt++) {
            o[nt][0] *= a0; o[nt][1] *= a0;
            o[nt][2] *= a1; o[nt][3] *= a1;
        }

        // ---- O += P_h * (V_hi + V_lo), fp16 2-term ----
        #pragma unroll
        for (int c = 0; c < 4; c++) {
            uint32_t pa0 = pack_h2(sacc[2*c][0],   sacc[2*c][1]);
            uint32_t pa1 = pack_h2(sacc[2*c][2],   sacc[2*c][3]);
            uint32_t pa2 = pack_h2(sacc[2*c+1][0], sacc[2*c+1][1]);
            uint32_t pa3 = pack_h2(sacc[2*c+1][2], sacc[2*c+1][3]);
            #pragma unroll
            for (int dt = 0; dt < 8; dt++) {
                uint32_t vaddr = vs0 + ((c*16 + ((lane>>3)&1)*8 + (lane&7))*ALD
                                        + dt*16 + (lane>>4)*8)*2;
                uint32_t vh0,vh1,vh2,vh3, vl0,vl1,vl2,vl3;
                ldm4t(vh0,vh1,vh2,vh3, vaddr);
                ldm4t(vl0,vl1,vl2,vl3, vaddr + 128*2);
                mma_f16(o[2*dt],   pa0,pa1,pa2,pa3, vh0,vh1);
                mma_f16(o[2*dt],   pa0,pa1,pa2,pa3, vl0,vl1);
                mma_f16(o[2*dt+1], pa0,pa1,pa2,pa3, vh2,vh3);
                mma_f16(o[2*dt+1], pa0,pa1,pa2,pa3, vl2,vl3);
            }
        }
        __syncthreads();
    }

    // ---- normalize + fp16-split write into g_A2 [hi|lo] ----
    const float rn0 = 1.f / l0, rn1 = 1.f / l1;
    const int b = bh >> 4, h = bh & 15;
    const int row0 = q0 + wq + lr;
    const size_t rbase0 = (size_t)(b*S_ + row0) * AK2;
    const size_t rbase1 = (size_t)(b*S_ + row0 + 8) * AK2;
    #pragma unroll
    for (int nt = 0; nt < 16; nt++) {
        int col = h*DH_ + nt*8 + 2*lc;
        uint32_t h0, lo0, h1, lo1;
        split_pack_h(o[nt][0]*rn0, o[nt][1]*rn0, h0, lo0);
        split_pack_h(o[nt][2]*rn1, o[nt][3]*rn1, h1, lo1);
        *(uint32_t*)&g_A2[rbase0 + col]       = h0;
        *(uint32_t*)&g_A2[rbase0 + C_ + col]  = lo0;
        *(uint32_t*)&g_A2[rbase1 + col]       = h1;
        *(uint32_t*)&g_A2[rbase1 + C_ + col]  = lo1;
    }
}

// ---------------------------------------------------------------------------
extern "C" void kernel_launch(void* const* d_in, const int* in_sizes, int n_in,
                              void* d_out, int out_size) {
    const float* x     = (const float*)d_in[0];
    const float* Wqkv  = (const float*)d_in[1];
    const float* Wproj = (const float*)d_in[2];
    float* out = (float*)d_out;

    __half *a2_p, *b2_p, *b2p_p;
    cudaGetSymbolAddress((void**)&a2_p,  g_A2);
    cudaGetSymbolAddress((void**)&b2_p,  g_B2);
    cudaGetSymbolAddress((void**)&b2p_p, g_B2p);

    cudaFuncSetAttribute(gemm1_fused,
                         cudaFuncAttributeMaxDynamicSharedMemorySize, GEMM_SMEM);
    cudaFuncSetAttribute(gemm_f16_2term,
                         cudaFuncAttributeMaxDynamicSharedMemorySize, GEMM_SMEM);
    cudaFuncSetAttribute(attn_mma_kernel,
                         cudaFuncAttributeMaxDynamicSharedMemorySize, ATT_SMEM);

    // 1) mega-prep: rope table + all fp16 split conversions (one launch)
    prep_kernel<<<PREP_BLKS, 256>>>(x, Wqkv, Wproj);

    // 2) fused GEMM1: x @ Wqkv -> RoPE -> split -> g_Q2/K2/V2
    gemm1_fused<<<dim3((3*C_)/GBN, (B_*S_)/GBM), 256, GEMM_SMEM>>>(a2_p, b2_p);

    // 3) tensor-core causal flash attention -> writes fp16-split A2
    attn_mma_kernel<<<dim3(S_/ABR, B_*H_), 256, ATT_SMEM>>>();

    // 4) out = attn @ Wproj (separate g_B2p: no aliasing with Wqkv's g_B2)
    gemm_f16_2term<<<dim3(C_/GBN, (B_*S_)/GBM), 256, GEMM_SMEM>>>(
        a2_p, b2p_p, out, C_);
}

// round 16
// speedup vs baseline: 1.0686x; 1.0082x over previous
#include <cuda_runtime.h>
#include <cuda_bf16.h>
#include <cuda_fp16.h>
#include <math.h>
#include <stdint.h>

// Problem constants
#define B_   2
#define S_   2048
#define C_   2048
#define H_   16
#define DH_  128
// Dh^-0.5 * log2(e): softmax via exp2
#define QSCALE (0.08838834764831845f * 1.4426950408889634f)

// Scratch (device globals)
__device__ __half g_A2[(size_t)B_*S_*C_];        // [4096][2048] fp16 hi only
__device__ __half g_B2[(size_t)3*C_*2*C_];       // [6144][4096] Wqkv^T [hi|lo]
__device__ __half g_B2p[(size_t)C_*2*C_];        // [2048][4096] Wproj^T [hi|lo]
__device__ __nv_bfloat16 g_Q2[(size_t)B_*H_*S_*256];
__device__ __nv_bfloat16 g_K2[(size_t)B_*H_*S_*256];
__device__ __half        g_V2[(size_t)B_*H_*S_*256];   // fp16 [hi|lo]
__device__ float g_cos[S_*64];
__device__ float g_sin[S_*64];

#define AK2 (2*C_)        // 4096: row stride of B2/B2p

__device__ __forceinline__ uint32_t smem_u32(const void* p) {
    uint32_t a;
    asm("{ .reg .u64 t; cvta.to.shared.u64 t, %1; cvt.u32.u64 %0, t; }" : "=r"(a) : "l"(p));
    return a;
}
__device__ __forceinline__ void cp16(uint32_t dst, const void* src) {
    asm volatile("cp.async.cg.shared.global [%0], [%1], 16;" :: "r"(dst), "l"(src));
}
__device__ __forceinline__ void ldm4(uint32_t& r0, uint32_t& r1, uint32_t& r2,
                                     uint32_t& r3, uint32_t addr) {
    asm volatile("ldmatrix.sync.aligned.m8n8.x4.shared.b16 {%0,%1,%2,%3}, [%4];"
        : "=r"(r0), "=r"(r1), "=r"(r2), "=r"(r3) : "r"(addr));
}
__device__ __forceinline__ void ldm4t(uint32_t& r0, uint32_t& r1, uint32_t& r2,
                                      uint32_t& r3, uint32_t addr) {
    asm volatile("ldmatrix.sync.aligned.m8n8.x4.trans.shared.b16 {%0,%1,%2,%3}, [%4];"
        : "=r"(r0), "=r"(r1), "=r"(r2), "=r"(r3) : "r"(addr));
}
__device__ __forceinline__ void mma_bf16(float* c, uint32_t a0, uint32_t a1,
                                         uint32_t a2, uint32_t a3,
                                         uint32_t b0, uint32_t b1) {
    asm volatile("mma.sync.aligned.m16n8k16.row.col.f32.bf16.bf16.f32 "
        "{%0,%1,%2,%3}, {%4,%5,%6,%7}, {%8,%9}, {%0,%1,%2,%3};"
        : "+f"(c[0]), "+f"(c[1]), "+f"(c[2]), "+f"(c[3])
        : "r"(a0), "r"(a1), "r"(a2), "r"(a3), "r"(b0), "r"(b1));
}
__device__ __forceinline__ void mma_f16(float* c, uint32_t a0, uint32_t a1,
                                        uint32_t a2, uint32_t a3,
                                        uint32_t b0, uint32_t b1) {
    asm volatile("mma.sync.aligned.m16n8k16.row.col.f32.f16.f16.f32 "
        "{%0,%1,%2,%3}, {%4,%5,%6,%7}, {%8,%9}, {%0,%1,%2,%3};"
        : "+f"(c[0]), "+f"(c[1]), "+f"(c[2]), "+f"(c[3])
        : "r"(a0), "r"(a1), "r"(a2), "r"(a3), "r"(b0), "r"(b1));
}
__device__ __forceinline__ float fexp2(float x) {
    float r;
    asm("ex2.approx.ftz.f32 %0, %1;" : "=f"(r) : "f"(x));
    return r;
}
__device__ __forceinline__ void split_pack(float x, float y, uint32_t& hi, uint32_t& lo) {
    __nv_bfloat16 hx = __float2bfloat16(x);
    __nv_bfloat16 hy = __float2bfloat16(y);
    __nv_bfloat16 lx = __float2bfloat16(x - __bfloat162float(hx));
    __nv_bfloat16 ly = __float2bfloat16(y - __bfloat162float(hy));
    hi = (uint32_t)*(uint16_t*)&hx | ((uint32_t)*(uint16_t*)&hy << 16);
    lo = (uint32_t)*(uint16_t*)&lx | ((uint32_t)*(uint16_t*)&ly << 16);
}
__device__ __forceinline__ uint32_t pack_h2(float x, float y) {
    __half2 h = __floats2half2_rn(x, y);
    return *(uint32_t*)&h;
}
__device__ __forceinline__ void split_st(__nv_bfloat16* dst, int off, float v) {
    __nv_bfloat16 hi = __float2bfloat16(v);
    dst[off]       = hi;
    dst[off + 128] = __float2bfloat16(v - __bfloat162float(hi));
}
__device__ __forceinline__ void split_st_h(__half* dst, int off, float v) {
    __half hi = __float2half(v);
    dst[off]       = hi;
    dst[off + 128] = __float2half(v - __half2float(hi));
}

// ---------------------------------------------------------------------------
// Mega-prep: rope table + conv_A(hi only) + conv_B(Wqkv) + conv_B(Wproj)
// ---------------------------------------------------------------------------
#define PREP_ROPE_BLKS  512
#define PREP_CONVA_BLKS 8192
#define PREP_CBQ_BLKS   12288      // (6144/32)*(2048/32)
#define PREP_CBP_BLKS   4096       // (2048/32)*(2048/32)
#define PREP_BLKS (PREP_ROPE_BLKS + PREP_CONVA_BLKS + PREP_CBQ_BLKS + PREP_CBP_BLKS)

__device__ __forceinline__ void conv_B_body(const float* __restrict__ W, int N,
                                            __half* __restrict__ dst,
                                            int n0, int k0, int tid,
                                            float (*tile)[33]) {
    int tx = tid & 31, ty = tid >> 5;
    #pragma unroll
    for (int j = 0; j < 4; j++)
        tile[ty + 8*j][tx] = W[(size_t)(k0 + ty + 8*j) * N + n0 + tx];
    __syncthreads();
    #pragma unroll
    for (int j = 0; j < 4; j++) {
        int n = n0 + ty + 8*j;
        int k = k0 + tx;
        float v = tile[tx][ty + 8*j];
        __half hi = __float2half(v);
        __half lo = __float2half(v - __half2float(hi));
        size_t base = (size_t)n * AK2;
        dst[base + k]      = hi;
        dst[base + C_ + k] = lo;
    }
}

__global__ void __launch_bounds__(256) prep_kernel(
    const float* __restrict__ x,
    const float* __restrict__ Wqkv,
    const float* __restrict__ Wproj)
{
    __shared__ float tile[32][33];
    const int bx = blockIdx.x, tid = threadIdx.x;

    if (bx < PREP_ROPE_BLKS) {
        int idx = bx * 256 + tid;
        int s = idx >> 6, d = idx & 63;
        float invf = (float)pow(10000.0, -(double)d / 64.0);
        float ang  = (float)s * invf;
        double a = (double)ang;
        g_cos[idx] = (float)cos(a);
        g_sin[idx] = (float)sin(a);
    } else if (bx < PREP_ROPE_BLKS + PREP_CONVA_BLKS) {
        int idx = (bx - PREP_ROPE_BLKS) * 256 + tid;
        int k4 = (idx & ((C_/4)-1)) * 4;
        int m  = idx >> 9;
        float4 v = *(const float4*)(x + (size_t)m * C_ + k4);
        uint32_t h0 = pack_h2(v.x, v.y), h1 = pack_h2(v.z, v.w);
        *(uint2*)&g_A2[(size_t)m * C_ + k4] = make_uint2(h0, h1);
    } else if (bx < PREP_ROPE_BLKS + PREP_CONVA_BLKS + PREP_CBQ_BLKS) {
        int bid = bx - (PREP_ROPE_BLKS + PREP_CONVA_BLKS);
        int n0 = (bid % 192) * 32, k0 = (bid / 192) * 32;
        conv_B_body(Wqkv, 3*C_, g_B2, n0, k0, tid, tile);
    } else {
        int bid = bx - (PREP_ROPE_BLKS + PREP_CONVA_BLKS + PREP_CBQ_BLKS);
        int n0 = (bid & 63) * 32, k0 = (bid >> 6) * 32;
        conv_B_body(Wproj, C_, g_B2p, n0, k0, tid, tile);
    }
}

// ---------------------------------------------------------------------------
// GEMM mainloop — R10/R13 structure; A stride = C_ (hi-only matrix).
// ---------------------------------------------------------------------------
#define GBM 128
#define GBN 128
#define GBK 64
#define LDT 72
#define OP_ELEMS (128*LDT)
#define NSTG 3
#define GEMM_NT 64                       // 4096/64
#define GEMM_SMEM (NSTG*2*OP_ELEMS*2)    // 110592 B

#define GEMM_MAINLOOP(A_, Bt_)                                                   \
    const int tid  = threadIdx.x;                                                \
    const int lane = tid & 31, wid = tid >> 5;                                   \
    const int wm = wid >> 2, wn = wid & 3;                                       \
    const int bm = blockIdx.y * GBM, bn = blockIdx.x * GBN;                      \
    const uint32_t aBase = smem_u32(gsm);                                        \
    const uint32_t bBase = smem_u32(gsm + NSTG*OP_ELEMS);                        \
    const uint32_t aRowSel = (lane & 15), aColSel = (lane >> 4) * 8;             \
    const uint32_t bRowSel = ((lane >> 4) * 8) + (lane & 7);                     \
    const uint32_t bColSel = ((lane >> 3) & 1) * 8;                              \
    const int rg = tid >> 3, cg8 = (tid & 7) * 8;                                \
    float acc[4][4][4];                                                          \
    _Pragma("unroll")                                                            \
    for (int i = 0; i < 4; i++)                                                  \
        _Pragma("unroll")                                                        \
        for (int j = 0; j < 4; j++)                                              \
            _Pragma("unroll")                                                    \
            for (int r = 0; r < 4; r++) acc[i][j][r] = 0.f;                      \
    auto issue_part = [&](int stg, int kt, int p) {                              \
        const int kv = kt * GBK;                                                 \
        const int koffA = kv & (C_-1);                                           \
        const int koffB = kv;                                                    \
        const uint32_t aD = aBase + stg * OP_ELEMS * 2;                          \
        const uint32_t bD = bBase + stg * OP_ELEMS * 2;                          \
        const int r = rg + p * 32;                                               \
        cp16(aD + (r*LDT + cg8)*2, A_  + (size_t)(bm + r)*C_  + koffA + cg8);    \
        cp16(bD + (r*LDT + cg8)*2, Bt_ + (size_t)(bn + r)*AK2 + koffB + cg8);    \
    };                                                                           \
    _Pragma("unroll")                                                            \
    for (int p = 0; p < 4; p++) issue_part(0, 0, p);                             \
    asm volatile("cp.async.commit_group;");                                      \
    _Pragma("unroll")                                                            \
    for (int p = 0; p < 4; p++) issue_part(1, 1, p);                             \
    asm volatile("cp.async.commit_group;");                                      \
    for (int kt = 0; kt < GEMM_NT; kt++) {                                       \
        if (kt < GEMM_NT - 1) asm volatile("cp.async.wait_group 1;");            \
        else                  asm volatile("cp.async.wait_group 0;");            \
        __syncthreads();                                                         \
        const bool pf = (kt + 2 < GEMM_NT);                                      \
        const int stg2 = (kt + 2) % NSTG;                                        \
        const uint32_t aS = aBase + (kt % NSTG) * OP_ELEMS * 2;                  \
        const uint32_t bS = bBase + (kt % NSTG) * OP_ELEMS * 2;                  \
        _Pragma("unroll")                                                        \
        for (int kc = 0; kc < 4; kc++) {                                         \
            if (pf) issue_part(stg2, kt + 2, kc);                                \
            uint32_t bf[4][2];                                                   \
            _Pragma("unroll")                                                    \
            for (int np = 0; np < 2; np++) {                                     \
                uint32_t addr = bS + ((wn*32 + np*16 + bRowSel) * LDT            \
                                      + kc*16 + bColSel) * 2;                    \
                uint32_t r0, r1, r2, r3;                                         \
                ldm4(r0, r1, r2, r3, addr);                                      \
                bf[np*2+0][0] = r0; bf[np*2+0][1] = r1;                          \
                bf[np*2+1][0] = r2; bf[np*2+1][1] = r3;                          \
            }                                                                    \
            _Pragma("unroll")                                                    \
            for (int mt = 0; mt < 4; mt++) {                                     \
                uint32_t addr = aS + ((wm*64 + mt*16 + aRowSel) * LDT            \
                                      + kc*16 + aColSel) * 2;                    \
                uint32_t a0, a1, a2, a3;                                         \
                ldm4(a0, a1, a2, a3, addr);                                      \
                _Pragma("unroll")                                                \
                for (int nt = 0; nt < 4; nt++)                                   \
                    mma_f16(acc[mt][nt], a0, a1, a2, a3, bf[nt][0], bf[nt][1]);  \
            }                                                                    \
        }                                                                        \
        if (pf) asm volatile("cp.async.commit_group;");                          \
    }

// ---------------------------------------------------------------------------
// GEMM1 (fused): qkv tile -> RoPE + scale + split -> g_Q2/K2(bf16), g_V2(fp16)
// ---------------------------------------------------------------------------
#define STG_LD 129

__global__ void __launch_bounds__(256, 2) gemm1_fused(
    const __half* __restrict__ A, const __half* __restrict__ Bt)
{
    extern __shared__ __half gsm[];
    GEMM_MAINLOOP(A, Bt)

    __syncthreads();
    float* st = (float*)gsm;                    // 128 x 129 fp32 = 66048 B
    #pragma unroll
    for (int mt = 0; mt < 4; mt++) {
        const int r0 = wm*64 + mt*16 + (lane >> 2);
        #pragma unroll
        for (int nt = 0; nt < 4; nt++) {
            const int col = wn*32 + nt*8 + (lane & 3)*2;
            st[r0*STG_LD + col]       = acc[mt][nt][0];
            st[r0*STG_LD + col + 1]   = acc[mt][nt][1];
            st[(r0+8)*STG_LD + col]   = acc[mt][nt][2];
            st[(r0+8)*STG_LD + col+1] = acc[mt][nt][3];
        }
    }
    __syncthreads();

    const int sec = bn >> 11;                   // 0=K, 1=Q, 2=V
    const int h   = (bn & (C_-1)) >> 7;
    const float scl = (sec == 1) ? QSCALE : 1.f;

    #pragma unroll
    for (int i = 0; i < 32; i++) {
        int p = tid + i*256;
        int r = p >> 6, d = p & 63;
        int grow = bm + r;
        int stok = grow & (S_-1), bb = grow >> 11;
        float t1 = st[r*STG_LD + d], t2 = st[r*STG_LD + d + 64];
        size_t orow = ((size_t)(bb*H_ + h) * S_ + stok) * 256;
        if (sec == 2) {
            split_st_h(g_V2 + orow, d, t1);
            split_st_h(g_V2 + orow, d + 64, t2);
        } else {
            float c  = g_cos[stok*64 + d];
            float sn = g_sin[stok*64 + d];
            float o1 = (t1*c - t2*sn) * scl;
            float o2 = (t2*c + t1*sn) * scl;
            __nv_bfloat16* dstArr = (sec == 0) ? g_K2 : g_Q2;
            split_st(dstArr + orow, d, o1);
            split_st(dstArr + orow, d + 64, o2);
        }
    }
}

// ---------------------------------------------------------------------------
// GEMM2 (plain): writes fp32 C
// ---------------------------------------------------------------------------
__global__ void __launch_bounds__(256, 2) gemm_f16_2term(
    const __half* __restrict__ A, const __half* __restrict__ Bt,
    float* __restrict__ C, int N)
{
    extern __shared__ __half gsm[];
    GEMM_MAINLOOP(A, Bt)

    #pragma unroll
    for (int mt = 0; mt < 4; mt++) {
        const int r0 = bm + wm*64 + mt*16 + (lane >> 2);
        #pragma unroll
        for (int nt = 0; nt < 4; nt++) {
            const int col = bn + wn*32 + nt*8 + (lane & 3)*2;
            *(float2*)(C + (size_t)r0 * N + col) =
                make_float2(acc[mt][nt][0], acc[mt][nt][1]);
            *(float2*)(C + (size_t)(r0 + 8) * N + col) =
                make_float2(acc[mt][nt][2], acc[mt][nt][3]);
        }
    }
}

// ---------------------------------------------------------------------------
// Tensor-core flash attention: QK bf16 3-term, PV fp16 2-term, exp2 softmax.
// Epilogue writes fp16 hi only into g_A2 (stride C_).
// ---------------------------------------------------------------------------
#define ABR 128
#define ABC 64
#define ALD 264
#define QS_ELEMS (ABR*ALD)
#define KV_ELEMS (ABC*ALD)
#define ATT_SMEM ((QS_ELEMS + 4*KV_ELEMS)*2)

__global__ void __launch_bounds__(256, 1) attn_mma_kernel() {
    extern __shared__ __nv_bfloat16 attsm[];
    __nv_bfloat16* Qs = attsm;
    __nv_bfloat16* Ks = attsm + QS_ELEMS;
    __nv_bfloat16* Vs = attsm + QS_ELEMS + 2*KV_ELEMS;   // holds fp16 bits

    const int tid = threadIdx.x, lane = tid & 31, wid = tid >> 5;
    const int qt = gridDim.x - 1 - blockIdx.x;
    const int bh = blockIdx.y;
    const int q0 = qt * ABR;
    const size_t gbase = (size_t)bh * S_ * 256;

    const uint32_t qsB = smem_u32(Qs), ksB = smem_u32(Ks), vsB = smem_u32(Vs);

    {
        const __nv_bfloat16* qsrc = g_Q2 + gbase + (size_t)q0 * 256;
        #pragma unroll
        for (int i = 0; i < 16; i++) {
            int ch = tid + i*256;
            int r = ch >> 5, c8 = (ch & 31) * 8;
            cp16(qsB + (r*ALD + c8)*2, qsrc + (size_t)r*256 + c8);
        }
        const __nv_bfloat16* ksrc = g_K2 + gbase;
        const __half*        vsrc = g_V2 + gbase;
        #pragma unroll
        for (int i = 0; i < 8; i++) {
            int ch = tid + i*256;
            int r = ch >> 5, c8 = (ch & 31) * 8;
            cp16(ksB + (r*ALD + c8)*2, ksrc + (size_t)r*256 + c8);
            cp16(vsB + (r*ALD + c8)*2, vsrc + (size_t)r*256 + c8);
        }
        asm volatile("cp.async.commit_group;");
    }

    const int lr = lane >> 2, lc = lane & 3;
    const int wq = wid * 16;

    float m0 = -1e30f, m1 = -1e30f, l0 = 0.f, l1 = 0.f;
    float o[16][4];
    #pragma unroll
    for (int i = 0; i < 16; i++)
        #pragma unroll
        for (int j = 0; j < 4; j++) o[i][j] = 0.f;

    const int nkb = 2*qt + 2;

    for (int kb = 0; kb < nkb; kb++) {
        const int s = kb & 1;
        if (kb + 1 < nkb) {
            const int ns = s ^ 1;
            const __nv_bfloat16* ksrc = g_K2 + gbase + (size_t)((kb+1)*ABC) * 256;
            const __half*        vsrc = g_V2 + gbase + (size_t)((kb+1)*ABC) * 256;
            uint32_t kd = ksB + ns*KV_ELEMS*2, vd = vsB + ns*KV_ELEMS*2;
            #pragma unroll
            for (int i = 0; i < 8; i++) {
                int ch = tid + i*256;
                int r = ch >> 5, c8 = (ch & 31) * 8;
                cp16(kd + (r*ALD + c8)*2, ksrc + (size_t)r*256 + c8);
                cp16(vd + (r*ALD + c8)*2, vsrc + (size_t)r*256 + c8);
            }
            asm volatile("cp.async.commit_group;");
            asm volatile("cp.async.wait_group 1;");
        } else {
            asm volatile("cp.async.wait_group 0;");
        }
        __syncthreads();

        const uint32_t ks0 = ksB + s*KV_ELEMS*2;
        const uint32_t vs0 = vsB + s*KV_ELEMS*2;

        float sacc[8][4];
        #pragma unroll
        for (int i = 0; i < 8; i++)
            #pragma unroll
            for (int j = 0; j < 4; j++) sacc[i][j] = 0.f;

        #pragma unroll
        for (int kc = 0; kc < 8; kc++) {
            uint32_t qaddr = qsB + ((wq + (lane & 15))*ALD + kc*16 + (lane >> 4)*8)*2;
            uint32_t qh0,qh1,qh2,qh3, ql0,ql1,ql2,ql3;
            ldm4(qh0,qh1,qh2,qh3, qaddr);
            ldm4(ql0,ql1,ql2,ql3, qaddr + 128*2);
            #pragma unroll
            for (int ntp = 0; ntp < 4; ntp++) {
                uint32_t baddr = ks0 + ((ntp*16 + (lane>>4)*8 + (lane&7))*ALD
                                        + kc*16 + ((lane>>3)&1)*8)*2;
                uint32_t h0,h1,h2,h3, e0,e1,e2,e3;
                ldm4(h0,h1,h2,h3, baddr);
                ldm4(e0,e1,e2,e3, baddr + 128*2);
                mma_bf16(sacc[2*ntp],   qh0,qh1,qh2,qh3, h0,h1);
                mma_bf16(sacc[2*ntp],   qh0,qh1,qh2,qh3, e0,e1);
                mma_bf16(sacc[2*ntp],   ql0,ql1,ql2,ql3, h0,h1);
                mma_bf16(sacc[2*ntp+1], qh0,qh1,qh2,qh3, h2,h3);
                mma_bf16(sacc[2*ntp+1], qh0,qh1,qh2,qh3, e2,e3);
                mma_bf16(sacc[2*ntp+1], ql0,ql1,ql2,ql3, h2,h3);
            }
        }

        const int r0 = q0 + wq + lr, r1 = r0 + 8;
        if (kb >= 2*qt) {
            #pragma unroll
            for (int nt = 0; nt < 8; nt++) {
                int key = kb*ABC + nt*8 + 2*lc;
                if (key     > r0) sacc[nt][0] = -1e30f;
                if (key + 1 > r0) sacc[nt][1] = -1e30f;
                if (key     > r1) sacc[nt][2] = -1e30f;
                if (key + 1 > r1) sacc[nt][3] = -1e30f;
            }
        }

        float mx0 = m0, mx1 = m1;
        #pragma unroll
        for (int nt = 0; nt < 8; nt++) {
            mx0 = fmaxf(mx0, fmaxf(sacc[nt][0], sacc[nt][1]));
            mx1 = fmaxf(mx1, fmaxf(sacc[nt][2], sacc[nt][3]));
        }
        mx0 = fmaxf(mx0, __shfl_xor_sync(0xffffffffu, mx0, 1));
        mx0 = fmaxf(mx0, __shfl_xor_sync(0xffffffffu, mx0, 2));
        mx1 = fmaxf(mx1, __shfl_xor_sync(0xffffffffu, mx1, 1));
        mx1 = fmaxf(mx1, __shfl_xor_sync(0xffffffffu, mx1, 2));
        float a0 = fexp2(m0 - mx0), a1 = fexp2(m1 - mx1);
        m0 = mx0; m1 = mx1;

        float s0 = 0.f, s1 = 0.f;
        #pragma unroll
        for (int nt = 0; nt < 8; nt++) {
            sacc[nt][0] = fexp2(sacc[nt][0] - m0); s0 += sacc[nt][0];
            sacc[nt][1] = fexp2(sacc[nt][1] - m0); s0 += sacc[nt][1];
            sacc[nt][2] = fexp2(sacc[nt][2] - m1); s1 += sacc[nt][2];
            sacc[nt][3] = fexp2(sacc[nt][3] - m1); s1 += sacc[nt][3];
        }
        s0 += __shfl_xor_sync(0xffffffffu, s0, 1);
        s0 += __shfl_xor_sync(0xffffffffu, s0, 2);
        s1 += __shfl_xor_sync(0xffffffffu, s1, 1);
        s1 += __shfl_xor_sync(0xffffffffu, s1, 2);
        l0 = l0 * a0 + s0;
        l1 = l1 * a1 + s1;

        #pragma unroll
        for (int nt = 0; nt < 16; nt++) {
            o[nt][0] *= a0; o[nt][1] *= a0;
            o[nt][2] *= a1; o[nt][3] *= a1;
        }

        // ---- O += P_h * (V_hi + V_lo), fp16 2-term ----
        #pragma unroll
        for (int c = 0; c < 4; c++) {
            uint32_t pa0 = pack_h2(sacc[2*c][0],   sacc[2*c][1]);
            uint32_t pa1 = pack_h2(sacc[2*c][2],   sacc[2*c][3]);
            uint32_t pa2 = pack_h2(sacc[2*c+1][0], sacc[2*c+1][1]);
            uint32_t pa3 = pack_h2(sacc[2*c+1][2], sacc[2*c+1][3]);
            #pragma unroll
            for (int dt = 0; dt < 8; dt++) {
                uint32_t vaddr = vs0 + ((c*16 + ((lane>>3)&1)*8 + (lane&7))*ALD
                                        + dt*16 + (lane>>4)*8)*2;
                uint32_t vh0,vh1,vh2,vh3, vl0,vl1,vl2,vl3;
                ldm4t(vh0,vh1,vh2,vh3, vaddr);
                ldm4t(vl0,vl1,vl2,vl3, vaddr + 128*2);
                mma_f16(o[2*dt],   pa0,pa1,pa2,pa3, vh0,vh1);
                mma_f16(o[2*dt],   pa0,pa1,pa2,pa3, vl0,vl1);
                mma_f16(o[2*dt+1], pa0,pa1,pa2,pa3, vh2,vh3);
                mma_f16(o[2*dt+1], pa0,pa1,pa2,pa3, vl2,vl3);
            }
        }
        __syncthreads();
    }

    // ---- normalize + fp16 hi write into g_A2 (stride C_) ----
    const float rn0 = 1.f / l0, rn1 = 1.f / l1;
    const int b = bh >> 4, h = bh & 15;
    const int row0 = q0 + wq + lr;
    const size_t rbase0 = (size_t)(b*S_ + row0) * C_;
    const size_t rbase1 = (size_t)(b*S_ + row0 + 8) * C_;
    #pragma unroll
    for (int nt = 0; nt < 16; nt++) {
        int col = h*DH_ + nt*8 + 2*lc;
        uint32_t h0 = pack_h2(o[nt][0]*rn0, o[nt][1]*rn0);
        uint32_t h1 = pack_h2(o[nt][2]*rn1, o[nt][3]*rn1);
        *(uint32_t*)&g_A2[rbase0 + col] = h0;
        *(uint32_t*)&g_A2[rbase1 + col] = h1;
    }
}

// ---------------------------------------------------------------------------
extern "C" void kernel_launch(void* const* d_in, const int* in_sizes, int n_in,
                              void* d_out, int out_size) {
    const float* x     = (const float*)d_in[0];
    const float* Wqkv  = (const float*)d_in[1];
    const float* Wproj = (const float*)d_in[2];
    float* out = (float*)d_out;

    __half *a2_p, *b2_p, *b2p_p;
    cudaGetSymbolAddress((void**)&a2_p,  g_A2);
    cudaGetSymbolAddress((void**)&b2_p,  g_B2);
    cudaGetSymbolAddress((void**)&b2p_p, g_B2p);

    cudaFuncSetAttribute(gemm1_fused,
                         cudaFuncAttributeMaxDynamicSharedMemorySize, GEMM_SMEM);
    cudaFuncSetAttribute(gemm_f16_2term,
                         cudaFuncAttributeMaxDynamicSharedMemorySize, GEMM_SMEM);
    cudaFuncSetAttribute(attn_mma_kernel,
                         cudaFuncAttributeMaxDynamicSharedMemorySize, ATT_SMEM);

    // 1) mega-prep: rope table + all fp16 split conversions (one launch)
    prep_kernel<<<PREP_BLKS, 256>>>(x, Wqkv, Wproj);

    // 2) fused GEMM1: x @ Wqkv -> RoPE -> split -> g_Q2/K2/V2
    gemm1_fused<<<dim3((3*C_)/GBN, (B_*S_)/GBM), 256, GEMM_SMEM>>>(a2_p, b2_p);

    // 3) tensor-core causal flash attention -> writes fp16 hi A2
    attn_mma_kernel<<<dim3(S_/ABR, B_*H_), 256, ATT_SMEM>>>();

    // 4) out = attn @ Wproj
    gemm_f16_2term<<<dim3(C_/GBN, (B_*S_)/GBM), 256, GEMM_SMEM>>>(
        a2_p, b2p_p, out, C_);
}

// round 17
// speedup vs baseline: 1.2414x; 1.1617x over previous
#include <cuda_runtime.h>
#include <cuda_bf16.h>
#include <cuda_fp16.h>
#include <math.h>
#include <stdint.h>

// Problem constants
#define B_   2
#define S_   2048
#define C_   2048
#define H_   16
#define DH_  128
// Dh^-0.5 * log2(e): softmax via exp2
#define QSCALE (0.08838834764831845f * 1.4426950408889634f)

// Scratch (device globals)
__device__ __half g_A2[(size_t)B_*S_*C_];        // [4096][2048] fp16 hi only
__device__ __half g_B2[(size_t)3*C_*2*C_];       // [6144][4096] Wqkv^T [hi|lo]
__device__ __half g_B2p[(size_t)C_*2*C_];        // [2048][4096] Wproj^T (hi used)
__device__ __nv_bfloat16 g_Q2[(size_t)B_*H_*S_*256];
__device__ __nv_bfloat16 g_K2[(size_t)B_*H_*S_*256];
__device__ __half        g_V2[(size_t)B_*H_*S_*256];   // fp16 (hi 128 cols used)
__device__ float g_cos[S_*64];
__device__ float g_sin[S_*64];

#define AK2 (2*C_)        // 4096: row stride of B2/B2p

__device__ __forceinline__ uint32_t smem_u32(const void* p) {
    uint32_t a;
    asm("{ .reg .u64 t; cvta.to.shared.u64 t, %1; cvt.u32.u64 %0, t; }" : "=r"(a) : "l"(p));
    return a;
}
__device__ __forceinline__ void cp16(uint32_t dst, const void* src) {
    asm volatile("cp.async.cg.shared.global [%0], [%1], 16;" :: "r"(dst), "l"(src));
}
__device__ __forceinline__ void ldm4(uint32_t& r0, uint32_t& r1, uint32_t& r2,
                                     uint32_t& r3, uint32_t addr) {
    asm volatile("ldmatrix.sync.aligned.m8n8.x4.shared.b16 {%0,%1,%2,%3}, [%4];"
        : "=r"(r0), "=r"(r1), "=r"(r2), "=r"(r3) : "r"(addr));
}
__device__ __forceinline__ void ldm4t(uint32_t& r0, uint32_t& r1, uint32_t& r2,
                                      uint32_t& r3, uint32_t addr) {
    asm volatile("ldmatrix.sync.aligned.m8n8.x4.trans.shared.b16 {%0,%1,%2,%3}, [%4];"
        : "=r"(r0), "=r"(r1), "=r"(r2), "=r"(r3) : "r"(addr));
}
__device__ __forceinline__ void mma_bf16(float* c, uint32_t a0, uint32_t a1,
                                         uint32_t a2, uint32_t a3,
                                         uint32_t b0, uint32_t b1) {
    asm volatile("mma.sync.aligned.m16n8k16.row.col.f32.bf16.bf16.f32 "
        "{%0,%1,%2,%3}, {%4,%5,%6,%7}, {%8,%9}, {%0,%1,%2,%3};"
        : "+f"(c[0]), "+f"(c[1]), "+f"(c[2]), "+f"(c[3])
        : "r"(a0), "r"(a1), "r"(a2), "r"(a3), "r"(b0), "r"(b1));
}
__device__ __forceinline__ void mma_f16(float* c, uint32_t a0, uint32_t a1,
                                        uint32_t a2, uint32_t a3,
                                        uint32_t b0, uint32_t b1) {
    asm volatile("mma.sync.aligned.m16n8k16.row.col.f32.f16.f16.f32 "
        "{%0,%1,%2,%3}, {%4,%5,%6,%7}, {%8,%9}, {%0,%1,%2,%3};"
        : "+f"(c[0]), "+f"(c[1]), "+f"(c[2]), "+f"(c[3])
        : "r"(a0), "r"(a1), "r"(a2), "r"(a3), "r"(b0), "r"(b1));
}
__device__ __forceinline__ float fexp2(float x) {
    float r;
    asm("ex2.approx.ftz.f32 %0, %1;" : "=f"(r) : "f"(x));
    return r;
}
__device__ __forceinline__ void split_pack(float x, float y, uint32_t& hi, uint32_t& lo) {
    __nv_bfloat16 hx = __float2bfloat16(x);
    __nv_bfloat16 hy = __float2bfloat16(y);
    __nv_bfloat16 lx = __float2bfloat16(x - __bfloat162float(hx));
    __nv_bfloat16 ly = __float2bfloat16(y - __bfloat162float(hy));
    hi = (uint32_t)*(uint16_t*)&hx | ((uint32_t)*(uint16_t*)&hy << 16);
    lo = (uint32_t)*(uint16_t*)&lx | ((uint32_t)*(uint16_t*)&ly << 16);
}
__device__ __forceinline__ uint32_t pack_h2(float x, float y) {
    __half2 h = __floats2half2_rn(x, y);
    return *(uint32_t*)&h;
}
__device__ __forceinline__ void split_st(__nv_bfloat16* dst, int off, float v) {
    __nv_bfloat16 hi = __float2bfloat16(v);
    dst[off]       = hi;
    dst[off + 128] = __float2bfloat16(v - __bfloat162float(hi));
}

// ---------------------------------------------------------------------------
// Mega-prep: rope table + conv_A(hi) + conv_B(Wqkv, hi+lo) + conv_B(Wproj, hi)
// ---------------------------------------------------------------------------
#define PREP_ROPE_BLKS  512
#define PREP_CONVA_BLKS 8192
#define PREP_CBQ_BLKS   12288      // (6144/32)*(2048/32)
#define PREP_CBP_BLKS   4096       // (2048/32)*(2048/32)
#define PREP_BLKS (PREP_ROPE_BLKS + PREP_CONVA_BLKS + PREP_CBQ_BLKS + PREP_CBP_BLKS)

__device__ __forceinline__ void conv_B_body(const float* __restrict__ W, int N,
                                            __half* __restrict__ dst, bool wlo,
                                            int n0, int k0, int tid,
                                            float (*tile)[33]) {
    int tx = tid & 31, ty = tid >> 5;
    #pragma unroll
    for (int j = 0; j < 4; j++)
        tile[ty + 8*j][tx] = W[(size_t)(k0 + ty + 8*j) * N + n0 + tx];
    __syncthreads();
    #pragma unroll
    for (int j = 0; j < 4; j++) {
        int n = n0 + ty + 8*j;
        int k = k0 + tx;
        float v = tile[tx][ty + 8*j];
        __half hi = __float2half(v);
        size_t base = (size_t)n * AK2;
        dst[base + k] = hi;
        if (wlo) dst[base + C_ + k] = __float2half(v - __half2float(hi));
    }
}

__global__ void __launch_bounds__(256) prep_kernel(
    const float* __restrict__ x,
    const float* __restrict__ Wqkv,
    const float* __restrict__ Wproj)
{
    __shared__ float tile[32][33];
    const int bx = blockIdx.x, tid = threadIdx.x;

    if (bx < PREP_ROPE_BLKS) {
        int idx = bx * 256 + tid;
        int s = idx >> 6, d = idx & 63;
        float invf = (float)pow(10000.0, -(double)d / 64.0);
        float ang  = (float)s * invf;
        double a = (double)ang;
        g_cos[idx] = (float)cos(a);
        g_sin[idx] = (float)sin(a);
    } else if (bx < PREP_ROPE_BLKS + PREP_CONVA_BLKS) {
        int idx = (bx - PREP_ROPE_BLKS) * 256 + tid;
        int k4 = (idx & ((C_/4)-1)) * 4;
        int m  = idx >> 9;
        float4 v = *(const float4*)(x + (size_t)m * C_ + k4);
        uint32_t h0 = pack_h2(v.x, v.y), h1 = pack_h2(v.z, v.w);
        *(uint2*)&g_A2[(size_t)m * C_ + k4] = make_uint2(h0, h1);
    } else if (bx < PREP_ROPE_BLKS + PREP_CONVA_BLKS + PREP_CBQ_BLKS) {
        int bid = bx - (PREP_ROPE_BLKS + PREP_CONVA_BLKS);
        int n0 = (bid % 192) * 32, k0 = (bid / 192) * 32;
        conv_B_body(Wqkv, 3*C_, g_B2, true, n0, k0, tid, tile);
    } else {
        int bid = bx - (PREP_ROPE_BLKS + PREP_CONVA_BLKS + PREP_CBQ_BLKS);
        int n0 = (bid & 63) * 32, k0 = (bid >> 6) * 32;
        conv_B_body(Wproj, C_, g_B2p, false, n0, k0, tid, tile);
    }
}

// ---------------------------------------------------------------------------
// GEMM mainloop — R10/R13 structure, parameterized chunk count NT_.
// A stride = C_ (hi-only), B stride = AK2. GEMM1: NT=64 (B [hi|lo]);
// GEMM2: NT=32 (B hi only).
// ---------------------------------------------------------------------------
#define GBM 128
#define GBN 128
#define GBK 64
#define LDT 72
#define OP_ELEMS (128*LDT)
#define NSTG 3
#define GEMM_SMEM (NSTG*2*OP_ELEMS*2)    // 110592 B

#define GEMM_MAINLOOP(A_, Bt_, NT_)                                              \
    const int tid  = threadIdx.x;                                                \
    const int lane = tid & 31, wid = tid >> 5;                                   \
    const int wm = wid >> 2, wn = wid & 3;                                       \
    const int bm = blockIdx.y * GBM, bn = blockIdx.x * GBN;                      \
    const uint32_t aBase = smem_u32(gsm);                                        \
    const uint32_t bBase = smem_u32(gsm + NSTG*OP_ELEMS);                        \
    const uint32_t aRowSel = (lane & 15), aColSel = (lane >> 4) * 8;             \
    const uint32_t bRowSel = ((lane >> 4) * 8) + (lane & 7);                     \
    const uint32_t bColSel = ((lane >> 3) & 1) * 8;                              \
    const int rg = tid >> 3, cg8 = (tid & 7) * 8;                                \
    float acc[4][4][4];                                                          \
    _Pragma("unroll")                                                            \
    for (int i = 0; i < 4; i++)                                                  \
        _Pragma("unroll")                                                        \
        for (int j = 0; j < 4; j++)                                              \
            _Pragma("unroll")                                                    \
            for (int r = 0; r < 4; r++) acc[i][j][r] = 0.f;                      \
    auto issue_part = [&](int stg, int kt, int p) {                              \
        const int kv = kt * GBK;                                                 \
        const int koffA = kv & (C_-1);                                           \
        const int koffB = kv;                                                    \
        const uint32_t aD = aBase + stg * OP_ELEMS * 2;                          \
        const uint32_t bD = bBase + stg * OP_ELEMS * 2;                          \
        const int r = rg + p * 32;                                               \
        cp16(aD + (r*LDT + cg8)*2, A_  + (size_t)(bm + r)*C_  + koffA + cg8);    \
        cp16(bD + (r*LDT + cg8)*2, Bt_ + (size_t)(bn + r)*AK2 + koffB + cg8);    \
    };                                                                           \
    _Pragma("unroll")                                                            \
    for (int p = 0; p < 4; p++) issue_part(0, 0, p);                             \
    asm volatile("cp.async.commit_group;");                                      \
    _Pragma("unroll")                                                            \
    for (int p = 0; p < 4; p++) issue_part(1, 1, p);                             \
    asm volatile("cp.async.commit_group;");                                      \
    for (int kt = 0; kt < (NT_); kt++) {                                         \
        if (kt < (NT_) - 1) asm volatile("cp.async.wait_group 1;");              \
        else                asm volatile("cp.async.wait_group 0;");              \
        __syncthreads();                                                         \
        const bool pf = (kt + 2 < (NT_));                                        \
        const int stg2 = (kt + 2) % NSTG;                                        \
        const uint32_t aS = aBase + (kt % NSTG) * OP_ELEMS * 2;                  \
        const uint32_t bS = bBase + (kt % NSTG) * OP_ELEMS * 2;                  \
        _Pragma("unroll")                                                        \
        for (int kc = 0; kc < 4; kc++) {                                         \
            if (pf) issue_part(stg2, kt + 2, kc);                                \
            uint32_t bf[4][2];                                                   \
            _Pragma("unroll")                                                    \
            for (int np = 0; np < 2; np++) {                                     \
                uint32_t addr = bS + ((wn*32 + np*16 + bRowSel) * LDT            \
                                      + kc*16 + bColSel) * 2;                    \
                uint32_t r0, r1, r2, r3;                                         \
                ldm4(r0, r1, r2, r3, addr);                                      \
                bf[np*2+0][0] = r0; bf[np*2+0][1] = r1;                          \
                bf[np*2+1][0] = r2; bf[np*2+1][1] = r3;                          \
            }                                                                    \
            _Pragma("unroll")                                                    \
            for (int mt = 0; mt < 4; mt++) {                                     \
                uint32_t addr = aS + ((wm*64 + mt*16 + aRowSel) * LDT            \
                                      + kc*16 + aColSel) * 2;                    \
                uint32_t a0, a1, a2, a3;                                         \
                ldm4(a0, a1, a2, a3, addr);                                      \
                _Pragma("unroll")                                                \
                for (int nt = 0; nt < 4; nt++)                                   \
                    mma_f16(acc[mt][nt], a0, a1, a2, a3, bf[nt][0], bf[nt][1]);  \
            }                                                                    \
        }                                                                        \
        if (pf) asm volatile("cp.async.commit_group;");                          \
    }

// ---------------------------------------------------------------------------
// GEMM1 (fused): qkv tile -> RoPE + scale + split -> g_Q2/K2(bf16), g_V2(fp16 hi)
// ---------------------------------------------------------------------------
#define STG_LD 129

__global__ void __launch_bounds__(256, 2) gemm1_fused(
    const __half* __restrict__ A, const __half* __restrict__ Bt)
{
    extern __shared__ __half gsm[];
    GEMM_MAINLOOP(A, Bt, 64)

    __syncthreads();
    float* st = (float*)gsm;                    // 128 x 129 fp32 = 66048 B
    #pragma unroll
    for (int mt = 0; mt < 4; mt++) {
        const int r0 = wm*64 + mt*16 + (lane >> 2);
        #pragma unroll
        for (int nt = 0; nt < 4; nt++) {
            const int col = wn*32 + nt*8 + (lane & 3)*2;
            st[r0*STG_LD + col]       = acc[mt][nt][0];
            st[r0*STG_LD + col + 1]   = acc[mt][nt][1];
            st[(r0+8)*STG_LD + col]   = acc[mt][nt][2];
            st[(r0+8)*STG_LD + col+1] = acc[mt][nt][3];
        }
    }
    __syncthreads();

    const int sec = bn >> 11;                   // 0=K, 1=Q, 2=V
    const int h   = (bn & (C_-1)) >> 7;
    const float scl = (sec == 1) ? QSCALE : 1.f;

    #pragma unroll
    for (int i = 0; i < 32; i++) {
        int p = tid + i*256;
        int r = p >> 6, d = p & 63;
        int grow = bm + r;
        int stok = grow & (S_-1), bb = grow >> 11;
        float t1 = st[r*STG_LD + d], t2 = st[r*STG_LD + d + 64];
        size_t orow = ((size_t)(bb*H_ + h) * S_ + stok) * 256;
        if (sec == 2) {
            g_V2[orow + d]      = __float2half(t1);
            g_V2[orow + d + 64] = __float2half(t2);
        } else {
            float c  = g_cos[stok*64 + d];
            float sn = g_sin[stok*64 + d];
            float o1 = (t1*c - t2*sn) * scl;
            float o2 = (t2*c + t1*sn) * scl;
            __nv_bfloat16* dstArr = (sec == 0) ? g_K2 : g_Q2;
            split_st(dstArr + orow, d, o1);
            split_st(dstArr + orow, d + 64, o2);
        }
    }
}

// ---------------------------------------------------------------------------
// GEMM2 (plain, pure fp16 hi·hi, K=2048): writes fp32 C
// ---------------------------------------------------------------------------
__global__ void __launch_bounds__(256, 2) gemm_f16_2term(
    const __half* __restrict__ A, const __half* __restrict__ Bt,
    float* __restrict__ C, int N)
{
    extern __shared__ __half gsm[];
    GEMM_MAINLOOP(A, Bt, 32)

    #pragma unroll
    for (int mt = 0; mt < 4; mt++) {
        const int r0 = bm + wm*64 + mt*16 + (lane >> 2);
        #pragma unroll
        for (int nt = 0; nt < 4; nt++) {
            const int col = bn + wn*32 + nt*8 + (lane & 3)*2;
            *(float2*)(C + (size_t)r0 * N + col) =
                make_float2(acc[mt][nt][0], acc[mt][nt][1]);
            *(float2*)(C + (size_t)(r0 + 8) * N + col) =
                make_float2(acc[mt][nt][2], acc[mt][nt][3]);
        }
    }
}

// ---------------------------------------------------------------------------
// Tensor-core flash attention: QK bf16 3-term, PV fp16 1-term, exp2 softmax.
// ---------------------------------------------------------------------------
#define ABR 128
#define ABC 64
#define ALD 264
#define QS_ELEMS (ABR*ALD)
#define KV_ELEMS (ABC*ALD)
#define ATT_SMEM ((QS_ELEMS + 4*KV_ELEMS)*2)

__global__ void __launch_bounds__(256, 1) attn_mma_kernel() {
    extern __shared__ __nv_bfloat16 attsm[];
    __nv_bfloat16* Qs = attsm;
    __nv_bfloat16* Ks = attsm + QS_ELEMS;
    __nv_bfloat16* Vs = attsm + QS_ELEMS + 2*KV_ELEMS;   // fp16 bits, hi 128 cols

    const int tid = threadIdx.x, lane = tid & 31, wid = tid >> 5;
    const int qt = gridDim.x - 1 - blockIdx.x;
    const int bh = blockIdx.y;
    const int q0 = qt * ABR;
    const size_t gbase = (size_t)bh * S_ * 256;

    const uint32_t qsB = smem_u32(Qs), ksB = smem_u32(Ks), vsB = smem_u32(Vs);

    {
        const __nv_bfloat16* qsrc = g_Q2 + gbase + (size_t)q0 * 256;
        #pragma unroll
        for (int i = 0; i < 16; i++) {
            int ch = tid + i*256;
            int r = ch >> 5, c8 = (ch & 31) * 8;
            cp16(qsB + (r*ALD + c8)*2, qsrc + (size_t)r*256 + c8);
        }
        const __nv_bfloat16* ksrc = g_K2 + gbase;
        const __half*        vsrc = g_V2 + gbase;
        #pragma unroll
        for (int i = 0; i < 8; i++) {
            int ch = tid + i*256;
            int r = ch >> 5, c8 = (ch & 31) * 8;
            cp16(ksB + (r*ALD + c8)*2, ksrc + (size_t)r*256 + c8);
        }
        #pragma unroll
        for (int i = 0; i < 4; i++) {          // V: hi 128 cols only
            int ch = tid + i*256;
            int r = ch >> 4, c8 = (ch & 15) * 8;
            cp16(vsB + (r*ALD + c8)*2, vsrc + (size_t)r*256 + c8);
        }
        asm volatile("cp.async.commit_group;");
    }

    const int lr = lane >> 2, lc = lane & 3;
    const int wq = wid * 16;

    float m0 = -1e30f, m1 = -1e30f, l0 = 0.f, l1 = 0.f;
    float o[16][4];
    #pragma unroll
    for (int i = 0; i < 16; i++)
        #pragma unroll
        for (int j = 0; j < 4; j++) o[i][j] = 0.f;

    const int nkb = 2*qt + 2;

    for (int kb = 0; kb < nkb; kb++) {
        const int s = kb & 1;
        if (kb + 1 < nkb) {
            const int ns = s ^ 1;
            const __nv_bfloat16* ksrc = g_K2 + gbase + (size_t)((kb+1)*ABC) * 256;
            const __half*        vsrc = g_V2 + gbase + (size_t)((kb+1)*ABC) * 256;
            uint32_t kd = ksB + ns*KV_ELEMS*2, vd = vsB + ns*KV_ELEMS*2;
            #pragma unroll
            for (int i = 0; i < 8; i++) {
                int ch = tid + i*256;
                int r = ch >> 5, c8 = (ch & 31) * 8;
                cp16(kd + (r*ALD + c8)*2, ksrc + (size_t)r*256 + c8);
            }
            #pragma unroll
            for (int i = 0; i < 4; i++) {      // V: hi 128 cols only
                int ch = tid + i*256;
                int r = ch >> 4, c8 = (ch & 15) * 8;
                cp16(vd + (r*ALD + c8)*2, vsrc + (size_t)r*256 + c8);
            }
            asm volatile("cp.async.commit_group;");
            asm volatile("cp.async.wait_group 1;");
        } else {
            asm volatile("cp.async.wait_group 0;");
        }
        __syncthreads();

        const uint32_t ks0 = ksB + s*KV_ELEMS*2;
        const uint32_t vs0 = vsB + s*KV_ELEMS*2;

        float sacc[8][4];
        #pragma unroll
        for (int i = 0; i < 8; i++)
            #pragma unroll
            for (int j = 0; j < 4; j++) sacc[i][j] = 0.f;

        #pragma unroll
        for (int kc = 0; kc < 8; kc++) {
            uint32_t qaddr = qsB + ((wq + (lane & 15))*ALD + kc*16 + (lane >> 4)*8)*2;
            uint32_t qh0,qh1,qh2,qh3, ql0,ql1,ql2,ql3;
            ldm4(qh0,qh1,qh2,qh3, qaddr);
            ldm4(ql0,ql1,ql2,ql3, qaddr + 128*2);
            #pragma unroll
            for (int ntp = 0; ntp < 4; ntp++) {
                uint32_t baddr = ks0 + ((ntp*16 + (lane>>4)*8 + (lane&7))*ALD
                                        + kc*16 + ((lane>>3)&1)*8)*2;
                uint32_t h0,h1,h2,h3, e0,e1,e2,e3;
                ldm4(h0,h1,h2,h3, baddr);
                ldm4(e0,e1,e2,e3, baddr + 128*2);
                mma_bf16(sacc[2*ntp],   qh0,qh1,qh2,qh3, h0,h1);
                mma_bf16(sacc[2*ntp],   qh0,qh1,qh2,qh3, e0,e1);
                mma_bf16(sacc[2*ntp],   ql0,ql1,ql2,ql3, h0,h1);
                mma_bf16(sacc[2*ntp+1], qh0,qh1,qh2,qh3, h2,h3);
                mma_bf16(sacc[2*ntp+1], qh0,qh1,qh2,qh3, e2,e3);
                mma_bf16(sacc[2*ntp+1], ql0,ql1,ql2,ql3, h2,h3);
            }
        }

        const int r0 = q0 + wq + lr, r1 = r0 + 8;
        if (kb >= 2*qt) {
            #pragma unroll
            for (int nt = 0; nt < 8; nt++) {
                int key = kb*ABC + nt*8 + 2*lc;
                if (key     > r0) sacc[nt][0] = -1e30f;
                if (key + 1 > r0) sacc[nt][1] = -1e30f;
                if (key     > r1) sacc[nt][2] = -1e30f;
                if (key + 1 > r1) sacc[nt][3] = -1e30f;
            }
        }

        float mx0 = m0, mx1 = m1;
        #pragma unroll
        for (int nt = 0; nt < 8; nt++) {
            mx0 = fmaxf(mx0, fmaxf(sacc[nt][0], sacc[nt][1]));
            mx1 = fmaxf(mx1, fmaxf(sacc[nt][2], sacc[nt][3]));
        }
        mx0 = fmaxf(mx0, __shfl_xor_sync(0xffffffffu, mx0, 1));
        mx0 = fmaxf(mx0, __shfl_xor_sync(0xffffffffu, mx0, 2));
        mx1 = fmaxf(mx1, __shfl_xor_sync(0xffffffffu, mx1, 1));
        mx1 = fmaxf(mx1, __shfl_xor_sync(0xffffffffu, mx1, 2));
        float a0 = fexp2(m0 - mx0), a1 = fexp2(m1 - mx1);
        m0 = mx0; m1 = mx1;

        float s0 = 0.f, s1 = 0.f;
        #pragma unroll
        for (int nt = 0; nt < 8; nt++) {
            sacc[nt][0] = fexp2(sacc[nt][0] - m0); s0 += sacc[nt][0];
            sacc[nt][1] = fexp2(sacc[nt][1] - m0); s0 += sacc[nt][1];
            sacc[nt][2] = fexp2(sacc[nt][2] - m1); s1 += sacc[nt][2];
            sacc[nt][3] = fexp2(sacc[nt][3] - m1); s1 += sacc[nt][3];
        }
        s0 += __shfl_xor_sync(0xffffffffu, s0, 1);
        s0 += __shfl_xor_sync(0xffffffffu, s0, 2);
        s1 += __shfl_xor_sync(0xffffffffu, s1, 1);
        s1 += __shfl_xor_sync(0xffffffffu, s1, 2);
        l0 = l0 * a0 + s0;
        l1 = l1 * a1 + s1;

        #pragma unroll
        for (int nt = 0; nt < 16; nt++) {
            o[nt][0] *= a0; o[nt][1] *= a0;
            o[nt][2] *= a1; o[nt][3] *= a1;
        }

        // ---- O += P_h * V_hi (fp16 1-term) ----
        #pragma unroll
        for (int c = 0; c < 4; c++) {
            uint32_t pa0 = pack_h2(sacc[2*c][0],   sacc[2*c][1]);
            uint32_t pa1 = pack_h2(sacc[2*c][2],   sacc[2*c][3]);
            uint32_t pa2 = pack_h2(sacc[2*c+1][0], sacc[2*c+1][1]);
            uint32_t pa3 = pack_h2(sacc[2*c+1][2], sacc[2*c+1][3]);
            #pragma unroll
            for (int dt = 0; dt < 8; dt++) {
                uint32_t vaddr = vs0 + ((c*16 + ((lane>>3)&1)*8 + (lane&7))*ALD
                                        + dt*16 + (lane>>4)*8)*2;
                uint32_t vh0,vh1,vh2,vh3;
                ldm4t(vh0,vh1,vh2,vh3, vaddr);
                mma_f16(o[2*dt],   pa0,pa1,pa2,pa3, vh0,vh1);
                mma_f16(o[2*dt+1], pa0,pa1,pa2,pa3, vh2,vh3);
            }
        }
        __syncthreads();
    }

    // ---- normalize + fp16 hi write into g_A2 (stride C_) ----
    const float rn0 = 1.f / l0, rn1 = 1.f / l1;
    const int b = bh >> 4, h = bh & 15;
    const int row0 = q0 + wq + lr;
    const size_t rbase0 = (size_t)(b*S_ + row0) * C_;
    const size_t rbase1 = (size_t)(b*S_ + row0 + 8) * C_;
    #pragma unroll
    for (int nt = 0; nt < 16; nt++) {
        int col = h*DH_ + nt*8 + 2*lc;
        uint32_t h0 = pack_h2(o[nt][0]*rn0, o[nt][1]*rn0);
        uint32_t h1 = pack_h2(o[nt][2]*rn1, o[nt][3]*rn1);
        *(uint32_t*)&g_A2[rbase0 + col] = h0;
        *(uint32_t*)&g_A2[rbase1 + col] = h1;
    }
}

// ---------------------------------------------------------------------------
extern "C" void kernel_launch(void* const* d_in, const int* in_sizes, int n_in,
                              void* d_out, int out_size) {
    const float* x     = (const float*)d_in[0];
    const float* Wqkv  = (const float*)d_in[1];
    const float* Wproj = (const float*)d_in[2];
    float* out = (float*)d_out;

    __half *a2_p, *b2_p, *b2p_p;
    cudaGetSymbolAddress((void**)&a2_p,  g_A2);
    cudaGetSymbolAddress((void**)&b2_p,  g_B2);
    cudaGetSymbolAddress((void**)&b2p_p, g_B2p);

    cudaFuncSetAttribute(gemm1_fused,
                         cudaFuncAttributeMaxDynamicSharedMemorySize, GEMM_SMEM);
    cudaFuncSetAttribute(gemm_f16_2term,
                         cudaFuncAttributeMaxDynamicSharedMemorySize, GEMM_SMEM);
    cudaFuncSetAttribute(attn_mma_kernel,
                         cudaFuncAttributeMaxDynamicSharedMemorySize, ATT_SMEM);

    // 1) mega-prep: rope table + all fp16 split conversions (one launch)
    prep_kernel<<<PREP_BLKS, 256>>>(x, Wqkv, Wproj);

    // 2) fused GEMM1: x @ Wqkv -> RoPE -> split -> g_Q2/K2/V2
    gemm1_fused<<<dim3((3*C_)/GBN, (B_*S_)/GBM), 256, GEMM_SMEM>>>(a2_p, b2_p);

    // 3) tensor-core causal flash attention -> writes fp16 hi A2
    attn_mma_kernel<<<dim3(S_/ABR, B_*H_), 256, ATT_SMEM>>>();

    // 4) out = attn @ Wproj (pure fp16, K=2048)
    gemm_f16_2term<<<dim3(C_/GBN, (B_*S_)/GBM), 256, GEMM_SMEM>>>(
        a2_p, b2p_p, out, C_);
}